// round 1
// baseline (speedup 1.0000x reference)
#include <cuda_runtime.h>
#include <math.h>

#define Bb 32
#define Tt 500
#define Cc 512
#define Hh 8
#define Dd 64
#define Mrows (Bb*Tt)
#define NBUCKETS 49

// ---------------- scratch (static device globals; no allocation) ----------------
__device__ float g_qT[(size_t)Bb*Hh*Dd*Tt];   // [(b*H+h)*D + d][t]  (d-major for attn smem staging)
__device__ float g_kT[(size_t)Bb*Hh*Dd*Tt];   // same layout
__device__ float g_v [(size_t)Bb*Hh*Tt*Dd];   // [(b*H+h)*T + t][d]
__device__ float g_y [(size_t)Mrows*Cc];      // attention output (B,T,C)
__device__ float g_res [(size_t)Mrows*Cc];
__device__ float g_x1  [(size_t)Mrows*Cc];
__device__ float g_h   [(size_t)Mrows*2*Cc];
__device__ float g_res2[(size_t)Mrows*Cc];
__device__ unsigned char g_bucket[(size_t)Bb*Tt*Tt + 64];  // +pad for uchar4 overreads

// ---------------- bucket ids (piecewise_index + beta shift) ----------------
__global__ void __launch_bounds__(256) bucket_kernel(const int* __restrict__ ct) {
    int i = blockIdx.x * blockDim.x + threadIdx.x;
    if (i >= Bb*Tt*Tt) return;
    int b = i / (Tt*Tt);
    int r = i - b*(Tt*Tt);
    int t = r / Tt;
    int s = r - t*Tt;
    int2 c1 = ((const int2*)ct)[b*Tt + t];
    int2 c2 = ((const int2*)ct)[b*Tt + s];
    int dx = c1.x - c2.x, dy = c1.y - c2.y;
    float dist = sqrtf((float)(dx*dx + dy*dy));
    float rel = truncf(dist / 12.0f);        // PPP = 12
    float idx;
    if (rel <= 12.0f) {                      // alpha = 12; rel is integer-valued -> round(rel)=rel
        idx = rel;
    } else {                                 // 12 + log(rel/12)/log(8) * 12, clamped to 24
        idx = fminf(rintf(12.0f + logf(rel / 12.0f) * 5.7707801635558523f), 24.0f);
    }
    g_bucket[i] = (unsigned char)(int)(idx + 24.0f);   // + beta
}

// ---------------- generic SGEMM: C = A[MxK] @ W[KxN] + bias, templated epilogue ----------------
// MODE 0: scatter to q (transposed), k (transposed), v (normal)
// MODE 1/3: out = val + resid   MODE 2: out = gelu_exact(val)
template<int MODE>
__global__ void __launch_bounds__(256) sgemm_kernel(
    const float* __restrict__ A, const float* __restrict__ W,
    const float* __restrict__ bias, float* __restrict__ Cout,
    const float* __restrict__ resid, int M, int N, int K)
{
    __shared__ float Ast[16][64];   // [k][row]
    __shared__ float Bs [16][64];   // [k][col]
    const int tid = threadIdx.x;
    const int tx = tid & 15, ty = tid >> 4;
    const int m0 = blockIdx.y << 6, n0 = blockIdx.x << 6;
    const int arow = tid >> 2,  acol = (tid & 3) << 2;
    const int brow = tid >> 4,  bcol = (tid & 15) << 2;
    const float* Aptr = A + (size_t)(m0 + arow)*K + acol;
    const float* Wptr = W + (size_t)brow*N + n0 + bcol;

    float acc[4][4] = {};
    for (int k0 = 0; k0 < K; k0 += 16) {
        float4 av = *(const float4*)(Aptr + k0);
        float4 bv = *(const float4*)(Wptr + (size_t)k0*N);
        __syncthreads();
        Ast[acol+0][arow] = av.x;
        Ast[acol+1][arow] = av.y;
        Ast[acol+2][arow] = av.z;
        Ast[acol+3][arow] = av.w;
        *(float4*)&Bs[brow][bcol] = bv;
        __syncthreads();
#pragma unroll
        for (int kk = 0; kk < 16; kk++) {
            float4 a  = *(const float4*)&Ast[kk][ty << 2];
            float4 bb = *(const float4*)&Bs[kk][tx << 2];
            float av_[4] = {a.x, a.y, a.z, a.w};
            float bv_[4] = {bb.x, bb.y, bb.z, bb.w};
#pragma unroll
            for (int i = 0; i < 4; i++)
#pragma unroll
                for (int j = 0; j < 4; j++)
                    acc[i][j] += av_[i] * bv_[j];
        }
    }

#pragma unroll
    for (int i = 0; i < 4; i++) {
        int m = m0 + (ty << 2) + i;
        int b_ = m / Tt, t = m - b_*Tt;
#pragma unroll
        for (int j = 0; j < 4; j++) {
            int c = n0 + (tx << 2) + j;
            float val = acc[i][j] + bias[c];
            if (MODE == 0) {
                int sec = c >> 9, cc = c & 511, hh = cc >> 6, d = cc & 63;
                int bh = b_*Hh + hh;
                if (sec == 0)      g_qT[((size_t)bh*Dd + d)*Tt + t] = val;
                else if (sec == 1) g_kT[((size_t)bh*Dd + d)*Tt + t] = val;
                else               g_v [((size_t)bh*Tt + t)*Dd + d] = val;
            } else if (MODE == 2) {
                Cout[(size_t)m*N + c] = 0.5f * val * (1.0f + erff(val * 0.7071067811865475f));
            } else {
                Cout[(size_t)m*N + c] = val + resid[(size_t)m*N + c];
            }
        }
    }
}

// ---------------- fused flash attention with RPE bias ----------------
struct AttnSmem {
    float Qst[Dd][64];       // [d][qrow]
    float Kst[Dd][64];       // [d][kcol]
    float Vs [64][Dd];       // [kcol][d]
    float Ps [64][65];       // scores/probs, padded
    float row_m[64], row_l[64], row_scale[64];
    float rpe[64];           // 49 used
    unsigned char bk[64][64];
};

__global__ void __launch_bounds__(256) attn_kernel(const float* __restrict__ rpe_table) {
    extern __shared__ char smraw[];
    AttnSmem& sm = *reinterpret_cast<AttnSmem*>(smraw);
    const int tid = threadIdx.x;
    const int tx = tid & 15, ty = tid >> 4;
    const int qt = blockIdx.x;            // 0..7
    const int bh = blockIdx.y;            // b*8 + h
    const int b_ = bh >> 3, h = bh & 7;
    const int hp = bh >> 5, bp = bh & 31; // faithful replication of the torch view() scramble
    const int t0 = qt << 6;

    if (tid < NBUCKETS) sm.rpe[tid] = rpe_table[hp*NBUCKETS + tid];
    if (tid < 64) { sm.row_m[tid] = -INFINITY; sm.row_l[tid] = 0.0f; }

    // load Q tile (already d-major in gmem -> conflict-free float4 smem stores)
    {
        const float* qb = g_qT + (size_t)bh*Dd*Tt;
#pragma unroll
        for (int it = 0; it < 4; it++) {
            int f = tid + it*256;
            int d = f >> 4;
            int r4 = (f & 15) << 2;
            float4 v = make_float4(0.f,0.f,0.f,0.f);
            const float* p = qb + (size_t)d*Tt;
            if (t0 + r4 + 3 < Tt) v = *(const float4*)(p + t0 + r4);
            else {
                if (t0+r4+0 < Tt) v.x = p[t0+r4+0];
                if (t0+r4+1 < Tt) v.y = p[t0+r4+1];
                if (t0+r4+2 < Tt) v.z = p[t0+r4+2];
                if (t0+r4+3 < Tt) v.w = p[t0+r4+3];
            }
            *(float4*)&sm.Qst[d][r4] = v;
        }
    }

    float O[4][4] = {};
    const float* kb = g_kT + (size_t)bh*Dd*Tt;
    const float* vb = g_v  + (size_t)bh*Tt*Dd;
    const unsigned char* bkb = g_bucket + (size_t)bp*Tt*Tt;

    for (int s0 = 0; s0 < Tt; s0 += 64) {
        __syncthreads();   // previous chunk's PV done before overwriting tiles
        // K tile (transposed layout)
#pragma unroll
        for (int it = 0; it < 4; it++) {
            int f = tid + it*256;
            int d = f >> 4;
            int c4 = (f & 15) << 2;
            float4 v = make_float4(0.f,0.f,0.f,0.f);
            const float* p = kb + (size_t)d*Tt;
            if (s0 + c4 + 3 < Tt) v = *(const float4*)(p + s0 + c4);
            else {
                if (s0+c4+0 < Tt) v.x = p[s0+c4+0];
                if (s0+c4+1 < Tt) v.y = p[s0+c4+1];
                if (s0+c4+2 < Tt) v.z = p[s0+c4+2];
                if (s0+c4+3 < Tt) v.w = p[s0+c4+3];
            }
            *(float4*)&sm.Kst[d][c4] = v;
        }
        // V tile
#pragma unroll
        for (int it = 0; it < 4; it++) {
            int f = tid + it*256;
            int c = f >> 4;
            int d4 = (f & 15) << 2;
            float4 v = make_float4(0.f,0.f,0.f,0.f);
            if (s0 + c < Tt) v = *(const float4*)(vb + (size_t)(s0 + c)*Dd + d4);
            *(float4*)&sm.Vs[c][d4] = v;
        }
        // bucket tile (values always <= 48; OOB-masked cols handled by -inf below)
#pragma unroll
        for (int it = 0; it < 4; it++) {
            int f = tid + it*256;
            int r = f >> 4;
            int c4 = (f & 15) << 2;
            uchar4 u4 = make_uchar4(0,0,0,0);
            if (t0 + r < Tt && s0 + c4 < Tt)
                u4 = *(const uchar4*)(bkb + (size_t)(t0 + r)*Tt + s0 + c4);
            *(uchar4*)&sm.bk[r][c4] = u4;
        }
        __syncthreads();

        // S = Q@K^T * 1/8 + rpe[bucket]
        float acc[4][4] = {};
#pragma unroll
        for (int k = 0; k < Dd; k++) {
            float4 a  = *(const float4*)&sm.Qst[k][ty << 2];
            float4 bb = *(const float4*)&sm.Kst[k][tx << 2];
            float av_[4] = {a.x, a.y, a.z, a.w};
            float bv_[4] = {bb.x, bb.y, bb.z, bb.w};
#pragma unroll
            for (int i = 0; i < 4; i++)
#pragma unroll
                for (int j = 0; j < 4; j++)
                    acc[i][j] += av_[i] * bv_[j];
        }
#pragma unroll
        for (int i = 0; i < 4; i++) {
            int r = (ty << 2) + i;
#pragma unroll
            for (int j = 0; j < 4; j++) {
                int c = (tx << 2) + j;
                float sS = acc[i][j] * 0.125f + sm.rpe[sm.bk[r][c]];
                if (s0 + c >= Tt) sS = -INFINITY;
                sm.Ps[r][c] = sS;
            }
        }
        __syncthreads();

        // online softmax (4 threads per row)
        {
            int r = tid >> 2, qq = tid & 3;
            int cbase = qq << 4;
            float mx = -INFINITY;
#pragma unroll
            for (int u = 0; u < 16; u++) mx = fmaxf(mx, sm.Ps[r][cbase+u]);
            mx = fmaxf(mx, __shfl_xor_sync(0xffffffffu, mx, 1));
            mx = fmaxf(mx, __shfl_xor_sync(0xffffffffu, mx, 2));
            float m_old = sm.row_m[r];
            float m_new = fmaxf(m_old, mx);
            float ssum = 0.f;
#pragma unroll
            for (int u = 0; u < 16; u++) {
                float p = __expf(sm.Ps[r][cbase+u] - m_new);
                sm.Ps[r][cbase+u] = p;
                ssum += p;
            }
            ssum += __shfl_xor_sync(0xffffffffu, ssum, 1);
            ssum += __shfl_xor_sync(0xffffffffu, ssum, 2);
            if (qq == 0) {
                float sc = __expf(m_old - m_new);
                sm.row_scale[r] = sc;
                sm.row_l[r] = sm.row_l[r]*sc + ssum;
                sm.row_m[r] = m_new;
            }
        }
        __syncthreads();

        // O = O*scale + P@V
        {
            float sc[4];
#pragma unroll
            for (int i = 0; i < 4; i++) sc[i] = sm.row_scale[(ty<<2)+i];
#pragma unroll
            for (int i = 0; i < 4; i++)
#pragma unroll
                for (int j = 0; j < 4; j++) O[i][j] *= sc[i];
#pragma unroll
            for (int c = 0; c < 64; c++) {
                float4 v = *(const float4*)&sm.Vs[c][tx << 2];
                float vv[4] = {v.x, v.y, v.z, v.w};
#pragma unroll
                for (int i = 0; i < 4; i++) {
                    float p = sm.Ps[(ty<<2)+i][c];
#pragma unroll
                    for (int j = 0; j < 4; j++) O[i][j] += p * vv[j];
                }
            }
        }
    }

    // finalize: divide by l, store (B,T,C)
#pragma unroll
    for (int i = 0; i < 4; i++) {
        int r = (ty << 2) + i;
        int t = t0 + r;
        if (t < Tt) {
            float inv = 1.0f / sm.row_l[r];
            float4 o;
            o.x = O[i][0]*inv; o.y = O[i][1]*inv; o.z = O[i][2]*inv; o.w = O[i][3]*inv;
            *(float4*)&g_y[((size_t)(b_*Tt + t))*Cc + h*Dd + (tx << 2)] = o;
        }
    }
}

// ---------------- layernorm: one block per row of 512 ----------------
__global__ void __launch_bounds__(256) ln_kernel(const float* __restrict__ in,
    const float* __restrict__ w, const float* __restrict__ b, float* __restrict__ out)
{
    __shared__ float red[8];
    int row = blockIdx.x;
    const float* x = in + (size_t)row*Cc;
    int tid = threadIdx.x;
    float v0 = x[tid], v1 = x[tid + 256];
    float s = v0 + v1;
#pragma unroll
    for (int o = 16; o > 0; o >>= 1) s += __shfl_xor_sync(0xffffffffu, s, o);
    if ((tid & 31) == 0) red[tid >> 5] = s;
    __syncthreads();
    float tot = red[0]+red[1]+red[2]+red[3]+red[4]+red[5]+red[6]+red[7];
    float mean = tot * (1.0f/512.0f);
    float d0 = v0 - mean, d1 = v1 - mean;
    float s2 = d0*d0 + d1*d1;
#pragma unroll
    for (int o = 16; o > 0; o >>= 1) s2 += __shfl_xor_sync(0xffffffffu, s2, o);
    __syncthreads();
    if ((tid & 31) == 0) red[tid >> 5] = s2;
    __syncthreads();
    float tot2 = red[0]+red[1]+red[2]+red[3]+red[4]+red[5]+red[6]+red[7];
    float inv = rsqrtf(tot2 * (1.0f/512.0f) + 1e-5f);
    out[(size_t)row*Cc + tid]       = d0*inv*w[tid]       + b[tid];
    out[(size_t)row*Cc + tid + 256] = d1*inv*w[tid + 256] + b[tid + 256];
}

// ---------------- launch ----------------
extern "C" void kernel_launch(void* const* d_in, const int* in_sizes, int n_in,
                              void* d_out, int out_size) {
    (void)in_sizes; (void)n_in; (void)out_size;
    const float* x         = (const float*)d_in[0];
    const int*   ct        = (const int*)  d_in[1];
    const float* w_attn    = (const float*)d_in[2];
    const float* b_attn    = (const float*)d_in[3];
    const float* w_proj    = (const float*)d_in[4];
    const float* b_proj    = (const float*)d_in[5];
    const float* rpe_table = (const float*)d_in[6];
    const float* ln1_w     = (const float*)d_in[7];
    const float* ln1_b     = (const float*)d_in[8];
    const float* ln2_w     = (const float*)d_in[9];
    const float* ln2_b     = (const float*)d_in[10];
    const float* w_fc      = (const float*)d_in[11];
    const float* b_fc      = (const float*)d_in[12];
    const float* w_fc2     = (const float*)d_in[13];
    const float* b_fc2     = (const float*)d_in[14];
    float* out = (float*)d_out;

    float *y_, *res_, *x1_, *h_, *res2_;
    cudaGetSymbolAddress((void**)&y_,    g_y);
    cudaGetSymbolAddress((void**)&res_,  g_res);
    cudaGetSymbolAddress((void**)&x1_,   g_x1);
    cudaGetSymbolAddress((void**)&h_,    g_h);
    cudaGetSymbolAddress((void**)&res2_, g_res2);

    cudaFuncSetAttribute(attn_kernel, cudaFuncAttributeMaxDynamicSharedMemorySize,
                         (int)sizeof(AttnSmem));

    bucket_kernel<<<(Bb*Tt*Tt + 255)/256, 256>>>(ct);
    sgemm_kernel<0><<<dim3(24, 250), 256>>>(x, w_attn, b_attn, nullptr, nullptr,
                                            Mrows, 3*Cc, Cc);
    attn_kernel<<<dim3(8, Bb*Hh), 256, sizeof(AttnSmem)>>>(rpe_table);
    sgemm_kernel<1><<<dim3(8, 250), 256>>>(y_, w_proj, b_proj, res_, x,
                                           Mrows, Cc, Cc);
    ln_kernel<<<Mrows, 256>>>(res_, ln1_w, ln1_b, x1_);
    sgemm_kernel<2><<<dim3(16, 250), 256>>>(x1_, w_fc, b_fc, h_, nullptr,
                                            Mrows, 2*Cc, Cc);
    sgemm_kernel<3><<<dim3(8, 250), 256>>>(h_, w_fc2, b_fc2, res2_, x1_,
                                           Mrows, Cc, 2*Cc);
    ln_kernel<<<Mrows, 256>>>(res2_, ln2_w, ln2_b, out);
}

// round 2
// speedup vs baseline: 1.1398x; 1.1398x over previous
#include <cuda_runtime.h>
#include <math.h>

#define Bb 32
#define Tt 500
#define Cc 512
#define Hh 8
#define Dd 64
#define Mrows (Bb*Tt)
#define NBUCKETS 49

// ---------------- scratch (static device globals; no allocation) ----------------
__device__ float g_qT[(size_t)Bb*Hh*Dd*Tt];   // [(b*H+h)*D + d][t]  (d-major for attn smem staging)
__device__ float g_kT[(size_t)Bb*Hh*Dd*Tt];   // same layout
__device__ float g_v [(size_t)Bb*Hh*Tt*Dd];   // [(b*H+h)*T + t][d]
__device__ float g_y [(size_t)Mrows*Cc];      // attention output (B,T,C)
__device__ float g_res [(size_t)Mrows*Cc];
__device__ float g_x1  [(size_t)Mrows*Cc];
__device__ float g_h   [(size_t)Mrows*2*Cc];
__device__ float g_res2[(size_t)Mrows*Cc];
__device__ unsigned char g_bucket[(size_t)Bb*Tt*Tt + 64];  // +pad for uchar4 overreads

// ---------------- bucket ids (piecewise_index + beta shift) ----------------
__global__ void __launch_bounds__(256) bucket_kernel(const int* __restrict__ ct) {
    int i = blockIdx.x * blockDim.x + threadIdx.x;
    if (i >= Bb*Tt*Tt) return;
    int b = i / (Tt*Tt);
    int r = i - b*(Tt*Tt);
    int t = r / Tt;
    int s = r - t*Tt;
    int2 c1 = ((const int2*)ct)[b*Tt + t];
    int2 c2 = ((const int2*)ct)[b*Tt + s];
    int dx = c1.x - c2.x, dy = c1.y - c2.y;
    float dist = sqrtf((float)(dx*dx + dy*dy));
    float rel = truncf(dist / 12.0f);        // PPP = 12
    float idx;
    if (rel <= 12.0f) {                      // alpha = 12; rel is integer-valued -> round(rel)=rel
        idx = rel;
    } else {                                 // 12 + log(rel/12)/log(8) * 12, clamped to 24
        idx = fminf(rintf(12.0f + logf(rel / 12.0f) * 5.7707801635558523f), 24.0f);
    }
    g_bucket[i] = (unsigned char)(int)(idx + 24.0f);   // + beta
}

// ---------------- SGEMM 128x128x16, 8x8 per thread, register prefetch ----------------
// MODE 0: scatter to q (transposed), k (transposed), v (normal)
// MODE 1/3: out = val + resid   MODE 2: out = gelu_exact(val)
template<int MODE>
__global__ void __launch_bounds__(256) sgemm_kernel(
    const float* __restrict__ A, const float* __restrict__ W,
    const float* __restrict__ bias, float* __restrict__ Cout,
    const float* __restrict__ resid, int M, int N, int K)
{
    __shared__ float As[16][128];   // [k][m]
    __shared__ float Bs[16][128];   // [k][n]
    const int tid = threadIdx.x;
    const int tx = tid & 15, ty = tid >> 4;
    const int m0 = blockIdx.y << 7, n0 = blockIdx.x << 7;

    const int ar = tid >> 2;            // rows 0..63 (+64 second chunk)
    const int ac = (tid & 3) << 2;      // k-offset 0,4,8,12
    const int br = tid >> 5;            // k rows 0..7 (+8 second chunk)
    const int bc = (tid & 31) << 2;     // cols 0..124

    const float* Aptr = A + (size_t)(m0 + ar)*K + ac;
    const float* Wptr = W + (size_t)br*N + n0 + bc;

    float4 aR0 = *(const float4*)(Aptr);
    float4 aR1 = *(const float4*)(Aptr + (size_t)64*K);
    float4 bR0 = *(const float4*)(Wptr);
    float4 bR1 = *(const float4*)(Wptr + (size_t)8*N);

    float acc[8][8] = {};
    float a[8], b[8];

    for (int k0 = 0; k0 < K; k0 += 16) {
        __syncthreads();
        As[ac+0][ar]      = aR0.x;  As[ac+1][ar]      = aR0.y;
        As[ac+2][ar]      = aR0.z;  As[ac+3][ar]      = aR0.w;
        As[ac+0][ar+64]   = aR1.x;  As[ac+1][ar+64]   = aR1.y;
        As[ac+2][ar+64]   = aR1.z;  As[ac+3][ar+64]   = aR1.w;
        *(float4*)&Bs[br  ][bc] = bR0;
        *(float4*)&Bs[br+8][bc] = bR1;
        __syncthreads();
        if (k0 + 16 < K) {
            aR0 = *(const float4*)(Aptr + k0 + 16);
            aR1 = *(const float4*)(Aptr + (size_t)64*K + k0 + 16);
            bR0 = *(const float4*)(Wptr + (size_t)(k0+16)*N);
            bR1 = *(const float4*)(Wptr + (size_t)(k0+24)*N);
        }
#pragma unroll
        for (int kk = 0; kk < 16; kk++) {
            *(float4*)&a[0] = *(const float4*)&As[kk][ty << 3];
            *(float4*)&a[4] = *(const float4*)&As[kk][(ty << 3) + 4];
            *(float4*)&b[0] = *(const float4*)&Bs[kk][tx << 3];
            *(float4*)&b[4] = *(const float4*)&Bs[kk][(tx << 3) + 4];
#pragma unroll
            for (int i = 0; i < 8; i++)
#pragma unroll
                for (int j = 0; j < 8; j++)
                    acc[i][j] += a[i] * b[j];
        }
    }

    // epilogue
#pragma unroll
    for (int i = 0; i < 8; i++) {
        int m = m0 + (ty << 3) + i;
        int b_ = m / Tt, t = m - b_*Tt;
        if (MODE == 0) {
#pragma unroll
            for (int j = 0; j < 8; j++) {
                int c = n0 + (tx << 3) + j;
                float val = acc[i][j] + bias[c];
                int sec = c >> 9, cc = c & 511, hh = cc >> 6, d = cc & 63;
                int bh = b_*Hh + hh;
                if (sec == 0)      g_qT[((size_t)bh*Dd + d)*Tt + t] = val;
                else if (sec == 1) g_kT[((size_t)bh*Dd + d)*Tt + t] = val;
                else               g_v [((size_t)bh*Tt + t)*Dd + d] = val;
            }
        } else {
#pragma unroll
            for (int jj = 0; jj < 2; jj++) {
                int c = n0 + (tx << 3) + (jj << 2);
                float4 o;
                float vv[4];
#pragma unroll
                for (int u = 0; u < 4; u++)
                    vv[u] = acc[i][(jj << 2) + u] + bias[c + u];
                if (MODE == 2) {
#pragma unroll
                    for (int u = 0; u < 4; u++)
                        vv[u] = 0.5f * vv[u] * (1.0f + erff(vv[u] * 0.7071067811865475f));
                } else {
                    float4 r = *(const float4*)(resid + (size_t)m*N + c);
                    vv[0] += r.x; vv[1] += r.y; vv[2] += r.z; vv[3] += r.w;
                }
                o.x = vv[0]; o.y = vv[1]; o.z = vv[2]; o.w = vv[3];
                *(float4*)(Cout + (size_t)m*N + c) = o;
            }
        }
    }
}

// ---------------- fused flash attention with RPE bias ----------------
struct AttnSmem {
    float Qst[Dd][64];       // [d][qrow]
    float Kst[Dd][64];       // [d][kcol]
    float Vs [64][Dd];       // [kcol][d]
    float Ps [64][65];       // scores/probs, padded
    float row_m[64], row_l[64], row_scale[64];
    float rpe[64];           // 49 used
    unsigned char bk[64][64];
};

__global__ void __launch_bounds__(256) attn_kernel(const float* __restrict__ rpe_table) {
    extern __shared__ char smraw[];
    AttnSmem& sm = *reinterpret_cast<AttnSmem*>(smraw);
    const int tid = threadIdx.x;
    const int tx = tid & 15, ty = tid >> 4;
    const int qt = blockIdx.x;            // 0..7
    const int bh = blockIdx.y;            // b*8 + h
    const int b_ = bh >> 3, h = bh & 7;
    const int hp = bh >> 5, bp = bh & 31; // faithful replication of the torch view() scramble
    const int t0 = qt << 6;

    if (tid < NBUCKETS) sm.rpe[tid] = rpe_table[hp*NBUCKETS + tid];
    if (tid < 64) { sm.row_m[tid] = -INFINITY; sm.row_l[tid] = 0.0f; }

    // load Q tile (already d-major in gmem -> conflict-free float4 smem stores)
    {
        const float* qb = g_qT + (size_t)bh*Dd*Tt;
#pragma unroll
        for (int it = 0; it < 4; it++) {
            int f = tid + it*256;
            int d = f >> 4;
            int r4 = (f & 15) << 2;
            float4 v = make_float4(0.f,0.f,0.f,0.f);
            const float* p = qb + (size_t)d*Tt;
            if (t0 + r4 + 3 < Tt) v = *(const float4*)(p + t0 + r4);
            else {
                if (t0+r4+0 < Tt) v.x = p[t0+r4+0];
                if (t0+r4+1 < Tt) v.y = p[t0+r4+1];
                if (t0+r4+2 < Tt) v.z = p[t0+r4+2];
                if (t0+r4+3 < Tt) v.w = p[t0+r4+3];
            }
            *(float4*)&sm.Qst[d][r4] = v;
        }
    }

    float O[4][4] = {};
    const float* kb = g_kT + (size_t)bh*Dd*Tt;
    const float* vb = g_v  + (size_t)bh*Tt*Dd;
    const unsigned char* bkb = g_bucket + (size_t)bp*Tt*Tt;

    for (int s0 = 0; s0 < Tt; s0 += 64) {
        __syncthreads();   // previous chunk's PV done before overwriting tiles
        // K tile (transposed layout)
#pragma unroll
        for (int it = 0; it < 4; it++) {
            int f = tid + it*256;
            int d = f >> 4;
            int c4 = (f & 15) << 2;
            float4 v = make_float4(0.f,0.f,0.f,0.f);
            const float* p = kb + (size_t)d*Tt;
            if (s0 + c4 + 3 < Tt) v = *(const float4*)(p + s0 + c4);
            else {
                if (s0+c4+0 < Tt) v.x = p[s0+c4+0];
                if (s0+c4+1 < Tt) v.y = p[s0+c4+1];
                if (s0+c4+2 < Tt) v.z = p[s0+c4+2];
                if (s0+c4+3 < Tt) v.w = p[s0+c4+3];
            }
            *(float4*)&sm.Kst[d][c4] = v;
        }
        // V tile
#pragma unroll
        for (int it = 0; it < 4; it++) {
            int f = tid + it*256;
            int c = f >> 4;
            int d4 = (f & 15) << 2;
            float4 v = make_float4(0.f,0.f,0.f,0.f);
            if (s0 + c < Tt) v = *(const float4*)(vb + (size_t)(s0 + c)*Dd + d4);
            *(float4*)&sm.Vs[c][d4] = v;
        }
        // bucket tile
#pragma unroll
        for (int it = 0; it < 4; it++) {
            int f = tid + it*256;
            int r = f >> 4;
            int c4 = (f & 15) << 2;
            uchar4 u4 = make_uchar4(0,0,0,0);
            if (t0 + r < Tt && s0 + c4 < Tt)
                u4 = *(const uchar4*)(bkb + (size_t)(t0 + r)*Tt + s0 + c4);
            *(uchar4*)&sm.bk[r][c4] = u4;
        }
        __syncthreads();

        // S = Q@K^T * 1/8 + rpe[bucket]
        float acc[4][4] = {};
#pragma unroll
        for (int k = 0; k < Dd; k++) {
            float4 a  = *(const float4*)&sm.Qst[k][ty << 2];
            float4 bb = *(const float4*)&sm.Kst[k][tx << 2];
            float av_[4] = {a.x, a.y, a.z, a.w};
            float bv_[4] = {bb.x, bb.y, bb.z, bb.w};
#pragma unroll
            for (int i = 0; i < 4; i++)
#pragma unroll
                for (int j = 0; j < 4; j++)
                    acc[i][j] += av_[i] * bv_[j];
        }
#pragma unroll
        for (int i = 0; i < 4; i++) {
            int r = (ty << 2) + i;
#pragma unroll
            for (int j = 0; j < 4; j++) {
                int c = (tx << 2) + j;
                float sS = acc[i][j] * 0.125f + sm.rpe[sm.bk[r][c]];
                if (s0 + c >= Tt) sS = -INFINITY;
                sm.Ps[r][c] = sS;
            }
        }
        __syncthreads();

        // online softmax (4 threads per row)
        {
            int r = tid >> 2, qq = tid & 3;
            int cbase = qq << 4;
            float mx = -INFINITY;
#pragma unroll
            for (int u = 0; u < 16; u++) mx = fmaxf(mx, sm.Ps[r][cbase+u]);
            mx = fmaxf(mx, __shfl_xor_sync(0xffffffffu, mx, 1));
            mx = fmaxf(mx, __shfl_xor_sync(0xffffffffu, mx, 2));
            float m_old = sm.row_m[r];
            float m_new = fmaxf(m_old, mx);
            float ssum = 0.f;
#pragma unroll
            for (int u = 0; u < 16; u++) {
                float p = __expf(sm.Ps[r][cbase+u] - m_new);
                sm.Ps[r][cbase+u] = p;
                ssum += p;
            }
            ssum += __shfl_xor_sync(0xffffffffu, ssum, 1);
            ssum += __shfl_xor_sync(0xffffffffu, ssum, 2);
            if (qq == 0) {
                float sc = __expf(m_old - m_new);
                sm.row_scale[r] = sc;
                sm.row_l[r] = sm.row_l[r]*sc + ssum;
                sm.row_m[r] = m_new;
            }
        }
        __syncthreads();

        // O = O*scale + P@V
        {
            float sc[4];
#pragma unroll
            for (int i = 0; i < 4; i++) sc[i] = sm.row_scale[(ty<<2)+i];
#pragma unroll
            for (int i = 0; i < 4; i++)
#pragma unroll
                for (int j = 0; j < 4; j++) O[i][j] *= sc[i];
#pragma unroll
            for (int c = 0; c < 64; c++) {
                float4 v = *(const float4*)&sm.Vs[c][tx << 2];
                float vv[4] = {v.x, v.y, v.z, v.w};
#pragma unroll
                for (int i = 0; i < 4; i++) {
                    float p = sm.Ps[(ty<<2)+i][c];
#pragma unroll
                    for (int j = 0; j < 4; j++) O[i][j] += p * vv[j];
                }
            }
        }
    }

    // finalize: divide by l, store (B,T,C)
#pragma unroll
    for (int i = 0; i < 4; i++) {
        int r = (ty << 2) + i;
        int t = t0 + r;
        if (t < Tt) {
            float inv = 1.0f / sm.row_l[r];
            float4 o;
            o.x = O[i][0]*inv; o.y = O[i][1]*inv; o.z = O[i][2]*inv; o.w = O[i][3]*inv;
            *(float4*)&g_y[((size_t)(b_*Tt + t))*Cc + h*Dd + (tx << 2)] = o;
        }
    }
}

// ---------------- layernorm: one block per row of 512 ----------------
__global__ void __launch_bounds__(256) ln_kernel(const float* __restrict__ in,
    const float* __restrict__ w, const float* __restrict__ b, float* __restrict__ out)
{
    __shared__ float red[8];
    int row = blockIdx.x;
    const float* x = in + (size_t)row*Cc;
    int tid = threadIdx.x;
    float v0 = x[tid], v1 = x[tid + 256];
    float s = v0 + v1;
#pragma unroll
    for (int o = 16; o > 0; o >>= 1) s += __shfl_xor_sync(0xffffffffu, s, o);
    if ((tid & 31) == 0) red[tid >> 5] = s;
    __syncthreads();
    float tot = red[0]+red[1]+red[2]+red[3]+red[4]+red[5]+red[6]+red[7];
    float mean = tot * (1.0f/512.0f);
    float d0 = v0 - mean, d1 = v1 - mean;
    float s2 = d0*d0 + d1*d1;
#pragma unroll
    for (int o = 16; o > 0; o >>= 1) s2 += __shfl_xor_sync(0xffffffffu, s2, o);
    __syncthreads();
    if ((tid & 31) == 0) red[tid >> 5] = s2;
    __syncthreads();
    float tot2 = red[0]+red[1]+red[2]+red[3]+red[4]+red[5]+red[6]+red[7];
    float inv = rsqrtf(tot2 * (1.0f/512.0f) + 1e-5f);
    out[(size_t)row*Cc + tid]       = d0*inv*w[tid]       + b[tid];
    out[(size_t)row*Cc + tid + 256] = d1*inv*w[tid + 256] + b[tid + 256];
}

// ---------------- launch ----------------
extern "C" void kernel_launch(void* const* d_in, const int* in_sizes, int n_in,
                              void* d_out, int out_size) {
    (void)in_sizes; (void)n_in; (void)out_size;
    const float* x         = (const float*)d_in[0];
    const int*   ct        = (const int*)  d_in[1];
    const float* w_attn    = (const float*)d_in[2];
    const float* b_attn    = (const float*)d_in[3];
    const float* w_proj    = (const float*)d_in[4];
    const float* b_proj    = (const float*)d_in[5];
    const float* rpe_table = (const float*)d_in[6];
    const float* ln1_w     = (const float*)d_in[7];
    const float* ln1_b     = (const float*)d_in[8];
    const float* ln2_w     = (const float*)d_in[9];
    const float* ln2_b     = (const float*)d_in[10];
    const float* w_fc      = (const float*)d_in[11];
    const float* b_fc      = (const float*)d_in[12];
    const float* w_fc2     = (const float*)d_in[13];
    const float* b_fc2     = (const float*)d_in[14];
    float* out = (float*)d_out;

    float *y_, *res_, *x1_, *h_, *res2_;
    cudaGetSymbolAddress((void**)&y_,    g_y);
    cudaGetSymbolAddress((void**)&res_,  g_res);
    cudaGetSymbolAddress((void**)&x1_,   g_x1);
    cudaGetSymbolAddress((void**)&h_,    g_h);
    cudaGetSymbolAddress((void**)&res2_, g_res2);

    cudaFuncSetAttribute(attn_kernel, cudaFuncAttributeMaxDynamicSharedMemorySize,
                         (int)sizeof(AttnSmem));

    bucket_kernel<<<(Bb*Tt*Tt + 255)/256, 256>>>(ct);
    sgemm_kernel<0><<<dim3(12, 125), 256>>>(x, w_attn, b_attn, nullptr, nullptr,
                                            Mrows, 3*Cc, Cc);
    attn_kernel<<<dim3(8, Bb*Hh), 256, sizeof(AttnSmem)>>>(rpe_table);
    sgemm_kernel<1><<<dim3(4, 125), 256>>>(y_, w_proj, b_proj, res_, x,
                                           Mrows, Cc, Cc);
    ln_kernel<<<Mrows, 256>>>(res_, ln1_w, ln1_b, x1_);
    sgemm_kernel<2><<<dim3(8, 125), 256>>>(x1_, w_fc, b_fc, h_, nullptr,
                                            Mrows, 2*Cc, Cc);
    sgemm_kernel<3><<<dim3(4, 125), 256>>>(h_, w_fc2, b_fc2, res2_, x1_,
                                           Mrows, Cc, 2*Cc);
    ln_kernel<<<Mrows, 256>>>(res2_, ln2_w, ln2_b, out);
}

// round 3
// speedup vs baseline: 1.1518x; 1.0105x over previous
#include <cuda_runtime.h>
#include <math.h>

#define Bb 32
#define Tt 500
#define Cc 512
#define Hh 8
#define Dd 64
#define Mrows (Bb*Tt)
#define NBUCKETS 49

// ---------------- scratch (static device globals; no allocation) ----------------
__device__ float g_qT[(size_t)Bb*Hh*Dd*Tt];   // [(b*H+h)*D + d][t]  (d-major for attn smem staging)
__device__ float g_kT[(size_t)Bb*Hh*Dd*Tt];   // same layout
__device__ float g_v [(size_t)Bb*Hh*Tt*Dd];   // [(b*H+h)*T + t][d]
__device__ float g_y [(size_t)Mrows*Cc];      // attention output (B,T,C)
__device__ float g_res [(size_t)Mrows*Cc];
__device__ float g_x1  [(size_t)Mrows*Cc];
__device__ float g_h   [(size_t)Mrows*2*Cc];
__device__ float g_res2[(size_t)Mrows*Cc];
__device__ unsigned char g_bucket[(size_t)Bb*Tt*Tt + 64];  // +pad for uchar4 overreads

// ---------------- bucket ids (piecewise_index + beta shift) ----------------
__global__ void __launch_bounds__(256) bucket_kernel(const int* __restrict__ ct) {
    int i = blockIdx.x * blockDim.x + threadIdx.x;
    if (i >= Bb*Tt*Tt) return;
    int b = i / (Tt*Tt);
    int r = i - b*(Tt*Tt);
    int t = r / Tt;
    int s = r - t*Tt;
    int2 c1 = ((const int2*)ct)[b*Tt + t];
    int2 c2 = ((const int2*)ct)[b*Tt + s];
    int dx = c1.x - c2.x, dy = c1.y - c2.y;
    float dist = sqrtf((float)(dx*dx + dy*dy));
    float rel = truncf(dist / 12.0f);        // PPP = 12
    float idx;
    if (rel <= 12.0f) {                      // alpha = 12
        idx = rel;
    } else {                                 // 12 + log(rel/12)/log(8) * 12, clamped to 24
        idx = fminf(rintf(12.0f + logf(rel / 12.0f) * 5.7707801635558523f), 24.0f);
    }
    g_bucket[i] = (unsigned char)(int)(idx + 24.0f);   // + beta
}

// ---------------- SGEMM 128x128x16, 8x8 per thread, double-buffered smem ----------------
// MODE 0: scatter to q (transposed), k (transposed), v (normal)
// MODE 1/3: out = val + resid   MODE 2: out = gelu_exact(val)
template<int MODE>
__global__ void __launch_bounds__(256, 2) sgemm_kernel(
    const float* __restrict__ A, const float* __restrict__ W,
    const float* __restrict__ bias, float* __restrict__ Cout,
    const float* __restrict__ resid, int M, int N, int K)
{
    __shared__ float As[2][16][128];   // [buf][k][m]
    __shared__ float Bs[2][16][128];   // [buf][k][n]
    const int tid = threadIdx.x;
    const int tx = tid & 15, ty = tid >> 4;
    const int m0 = blockIdx.y << 7, n0 = blockIdx.x << 7;

    const int ar = tid >> 2;            // rows 0..63 (+64 second chunk)
    const int ac = (tid & 3) << 2;      // k-offset 0,4,8,12
    const int br = tid >> 5;            // k rows 0..7 (+8 second chunk)
    const int bc = (tid & 31) << 2;     // cols 0..124

    const float* Aptr = A + (size_t)(m0 + ar)*K + ac;
    const float* Wptr = W + (size_t)br*N + n0 + bc;

    float4 aR0 = *(const float4*)(Aptr);
    float4 aR1 = *(const float4*)(Aptr + (size_t)64*K);
    float4 bR0 = *(const float4*)(Wptr);
    float4 bR1 = *(const float4*)(Wptr + (size_t)8*N);

    float acc[8][8] = {};
    float a[8], b[8];

    // store first tile into buffer 0
    As[0][ac+0][ar]    = aR0.x;  As[0][ac+1][ar]    = aR0.y;
    As[0][ac+2][ar]    = aR0.z;  As[0][ac+3][ar]    = aR0.w;
    As[0][ac+0][ar+64] = aR1.x;  As[0][ac+1][ar+64] = aR1.y;
    As[0][ac+2][ar+64] = aR1.z;  As[0][ac+3][ar+64] = aR1.w;
    *(float4*)&Bs[0][br  ][bc] = bR0;
    *(float4*)&Bs[0][br+8][bc] = bR1;
    __syncthreads();

    int buf = 0;
    for (int k0 = 16; ; k0 += 16) {
        const bool more = (k0 < K);
        if (more) {   // prefetch next tile (overlaps with compute below)
            aR0 = *(const float4*)(Aptr + k0);
            aR1 = *(const float4*)(Aptr + (size_t)64*K + k0);
            bR0 = *(const float4*)(Wptr + (size_t)k0*N);
            bR1 = *(const float4*)(Wptr + (size_t)(k0+8)*N);
        }
#pragma unroll
        for (int kk = 0; kk < 16; kk++) {
            *(float4*)&a[0] = *(const float4*)&As[buf][kk][ty << 3];
            *(float4*)&a[4] = *(const float4*)&As[buf][kk][(ty << 3) + 4];
            *(float4*)&b[0] = *(const float4*)&Bs[buf][kk][tx << 3];
            *(float4*)&b[4] = *(const float4*)&Bs[buf][kk][(tx << 3) + 4];
#pragma unroll
            for (int i = 0; i < 8; i++)
#pragma unroll
                for (int j = 0; j < 8; j++)
                    acc[i][j] += a[i] * b[j];
        }
        if (!more) break;
        buf ^= 1;
        As[buf][ac+0][ar]    = aR0.x;  As[buf][ac+1][ar]    = aR0.y;
        As[buf][ac+2][ar]    = aR0.z;  As[buf][ac+3][ar]    = aR0.w;
        As[buf][ac+0][ar+64] = aR1.x;  As[buf][ac+1][ar+64] = aR1.y;
        As[buf][ac+2][ar+64] = aR1.z;  As[buf][ac+3][ar+64] = aR1.w;
        *(float4*)&Bs[buf][br  ][bc] = bR0;
        *(float4*)&Bs[buf][br+8][bc] = bR1;
        __syncthreads();
    }

    // epilogue
#pragma unroll
    for (int i = 0; i < 8; i++) {
        int m = m0 + (ty << 3) + i;
        int b_ = m / Tt, t = m - b_*Tt;
        if (MODE == 0) {
#pragma unroll
            for (int j = 0; j < 8; j++) {
                int c = n0 + (tx << 3) + j;
                float val = acc[i][j] + bias[c];
                int sec = c >> 9, cc = c & 511, hh = cc >> 6, d = cc & 63;
                int bh = b_*Hh + hh;
                if (sec == 0)      g_qT[((size_t)bh*Dd + d)*Tt + t] = val;
                else if (sec == 1) g_kT[((size_t)bh*Dd + d)*Tt + t] = val;
                else               g_v [((size_t)bh*Tt + t)*Dd + d] = val;
            }
        } else {
#pragma unroll
            for (int jj = 0; jj < 2; jj++) {
                int c = n0 + (tx << 3) + (jj << 2);
                float4 o;
                float vv[4];
#pragma unroll
                for (int u = 0; u < 4; u++)
                    vv[u] = acc[i][(jj << 2) + u] + bias[c + u];
                if (MODE == 2) {
#pragma unroll
                    for (int u = 0; u < 4; u++)
                        vv[u] = 0.5f * vv[u] * (1.0f + erff(vv[u] * 0.7071067811865475f));
                } else {
                    float4 r = *(const float4*)(resid + (size_t)m*N + c);
                    vv[0] += r.x; vv[1] += r.y; vv[2] += r.z; vv[3] += r.w;
                }
                o.x = vv[0]; o.y = vv[1]; o.z = vv[2]; o.w = vv[3];
                *(float4*)(Cout + (size_t)m*N + c) = o;
            }
        }
    }
}

// ---------------- fused flash attention with RPE bias ----------------
struct AttnSmem {
    float Qst[Dd][64];       // [d][qrow]
    float Kst[Dd][64];       // [d][kcol]
    float Vs [64][Dd];       // [kcol][d]
    float Ps [64][65];       // scores/probs, padded
    float row_m[64], row_l[64], row_scale[64];
    float rpe[64];           // 49 used
    unsigned char bk[64][64];
};

__global__ void __launch_bounds__(256) attn_kernel(const float* __restrict__ rpe_table) {
    extern __shared__ char smraw[];
    AttnSmem& sm = *reinterpret_cast<AttnSmem*>(smraw);
    const int tid = threadIdx.x;
    const int tx = tid & 15, ty = tid >> 4;
    const int qt = blockIdx.x;            // 0..7
    const int bh = blockIdx.y;            // b*8 + h
    const int b_ = bh >> 3, h = bh & 7;
    const int hp = bh >> 5, bp = bh & 31; // faithful replication of the torch view() scramble
    const int t0 = qt << 6;

    if (tid < NBUCKETS) sm.rpe[tid] = rpe_table[hp*NBUCKETS + tid];
    if (tid < 64) { sm.row_m[tid] = -INFINITY; sm.row_l[tid] = 0.0f; }

    // load Q tile (already d-major in gmem -> conflict-free float4 smem stores)
    {
        const float* qb = g_qT + (size_t)bh*Dd*Tt;
#pragma unroll
        for (int it = 0; it < 4; it++) {
            int f = tid + it*256;
            int d = f >> 4;
            int r4 = (f & 15) << 2;
            float4 v = make_float4(0.f,0.f,0.f,0.f);
            const float* p = qb + (size_t)d*Tt;
            if (t0 + r4 + 3 < Tt) v = *(const float4*)(p + t0 + r4);
            else {
                if (t0+r4+0 < Tt) v.x = p[t0+r4+0];
                if (t0+r4+1 < Tt) v.y = p[t0+r4+1];
                if (t0+r4+2 < Tt) v.z = p[t0+r4+2];
                if (t0+r4+3 < Tt) v.w = p[t0+r4+3];
            }
            *(float4*)&sm.Qst[d][r4] = v;
        }
    }

    float O[4][4] = {};
    const float* kb = g_kT + (size_t)bh*Dd*Tt;
    const float* vb = g_v  + (size_t)bh*Tt*Dd;
    const unsigned char* bkb = g_bucket + (size_t)bp*Tt*Tt;

    for (int s0 = 0; s0 < Tt; s0 += 64) {
        __syncthreads();   // previous chunk's PV done before overwriting tiles
        // K tile (transposed layout)
#pragma unroll
        for (int it = 0; it < 4; it++) {
            int f = tid + it*256;
            int d = f >> 4;
            int c4 = (f & 15) << 2;
            float4 v = make_float4(0.f,0.f,0.f,0.f);
            const float* p = kb + (size_t)d*Tt;
            if (s0 + c4 + 3 < Tt) v = *(const float4*)(p + s0 + c4);
            else {
                if (s0+c4+0 < Tt) v.x = p[s0+c4+0];
                if (s0+c4+1 < Tt) v.y = p[s0+c4+1];
                if (s0+c4+2 < Tt) v.z = p[s0+c4+2];
                if (s0+c4+3 < Tt) v.w = p[s0+c4+3];
            }
            *(float4*)&sm.Kst[d][c4] = v;
        }
        // V tile
#pragma unroll
        for (int it = 0; it < 4; it++) {
            int f = tid + it*256;
            int c = f >> 4;
            int d4 = (f & 15) << 2;
            float4 v = make_float4(0.f,0.f,0.f,0.f);
            if (s0 + c < Tt) v = *(const float4*)(vb + (size_t)(s0 + c)*Dd + d4);
            *(float4*)&sm.Vs[c][d4] = v;
        }
        // bucket tile
#pragma unroll
        for (int it = 0; it < 4; it++) {
            int f = tid + it*256;
            int r = f >> 4;
            int c4 = (f & 15) << 2;
            uchar4 u4 = make_uchar4(0,0,0,0);
            if (t0 + r < Tt && s0 + c4 < Tt)
                u4 = *(const uchar4*)(bkb + (size_t)(t0 + r)*Tt + s0 + c4);
            *(uchar4*)&sm.bk[r][c4] = u4;
        }
        __syncthreads();

        // S = Q@K^T * 1/8 + rpe[bucket]
        float acc[4][4] = {};
#pragma unroll
        for (int k = 0; k < Dd; k++) {
            float4 a  = *(const float4*)&sm.Qst[k][ty << 2];
            float4 bb = *(const float4*)&sm.Kst[k][tx << 2];
            float av_[4] = {a.x, a.y, a.z, a.w};
            float bv_[4] = {bb.x, bb.y, bb.z, bb.w};
#pragma unroll
            for (int i = 0; i < 4; i++)
#pragma unroll
                for (int j = 0; j < 4; j++)
                    acc[i][j] += av_[i] * bv_[j];
        }
#pragma unroll
        for (int i = 0; i < 4; i++) {
            int r = (ty << 2) + i;
#pragma unroll
            for (int j = 0; j < 4; j++) {
                int c = (tx << 2) + j;
                float sS = acc[i][j] * 0.125f + sm.rpe[sm.bk[r][c]];
                if (s0 + c >= Tt) sS = -INFINITY;
                sm.Ps[r][c] = sS;
            }
        }
        __syncthreads();

        // online softmax (4 threads per row)
        {
            int r = tid >> 2, qq = tid & 3;
            int cbase = qq << 4;
            float mx = -INFINITY;
#pragma unroll
            for (int u = 0; u < 16; u++) mx = fmaxf(mx, sm.Ps[r][cbase+u]);
            mx = fmaxf(mx, __shfl_xor_sync(0xffffffffu, mx, 1));
            mx = fmaxf(mx, __shfl_xor_sync(0xffffffffu, mx, 2));
            float m_old = sm.row_m[r];
            float m_new = fmaxf(m_old, mx);
            float ssum = 0.f;
#pragma unroll
            for (int u = 0; u < 16; u++) {
                float p = __expf(sm.Ps[r][cbase+u] - m_new);
                sm.Ps[r][cbase+u] = p;
                ssum += p;
            }
            ssum += __shfl_xor_sync(0xffffffffu, ssum, 1);
            ssum += __shfl_xor_sync(0xffffffffu, ssum, 2);
            if (qq == 0) {
                float sc = __expf(m_old - m_new);
                sm.row_scale[r] = sc;
                sm.row_l[r] = sm.row_l[r]*sc + ssum;
                sm.row_m[r] = m_new;
            }
        }
        __syncthreads();

        // O = O*scale + P@V
        {
            float sc[4];
#pragma unroll
            for (int i = 0; i < 4; i++) sc[i] = sm.row_scale[(ty<<2)+i];
#pragma unroll
            for (int i = 0; i < 4; i++)
#pragma unroll
                for (int j = 0; j < 4; j++) O[i][j] *= sc[i];
#pragma unroll
            for (int c = 0; c < 64; c++) {
                float4 v = *(const float4*)&sm.Vs[c][tx << 2];
                float vv[4] = {v.x, v.y, v.z, v.w};
#pragma unroll
                for (int i = 0; i < 4; i++) {
                    float p = sm.Ps[(ty<<2)+i][c];
#pragma unroll
                    for (int j = 0; j < 4; j++) O[i][j] += p * vv[j];
                }
            }
        }
    }

    // finalize: divide by l, store (B,T,C)
#pragma unroll
    for (int i = 0; i < 4; i++) {
        int r = (ty << 2) + i;
        int t = t0 + r;
        if (t < Tt) {
            float inv = 1.0f / sm.row_l[r];
            float4 o;
            o.x = O[i][0]*inv; o.y = O[i][1]*inv; o.z = O[i][2]*inv; o.w = O[i][3]*inv;
            *(float4*)&g_y[((size_t)(b_*Tt + t))*Cc + h*Dd + (tx << 2)] = o;
        }
    }
}

// ---------------- layernorm: one block per row of 512 ----------------
__global__ void __launch_bounds__(256) ln_kernel(const float* __restrict__ in,
    const float* __restrict__ w, const float* __restrict__ b, float* __restrict__ out)
{
    __shared__ float red[8];
    int row = blockIdx.x;
    const float* x = in + (size_t)row*Cc;
    int tid = threadIdx.x;
    float v0 = x[tid], v1 = x[tid + 256];
    float s = v0 + v1;
#pragma unroll
    for (int o = 16; o > 0; o >>= 1) s += __shfl_xor_sync(0xffffffffu, s, o);
    if ((tid & 31) == 0) red[tid >> 5] = s;
    __syncthreads();
    float tot = red[0]+red[1]+red[2]+red[3]+red[4]+red[5]+red[6]+red[7];
    float mean = tot * (1.0f/512.0f);
    float d0 = v0 - mean, d1 = v1 - mean;
    float s2 = d0*d0 + d1*d1;
#pragma unroll
    for (int o = 16; o > 0; o >>= 1) s2 += __shfl_xor_sync(0xffffffffu, s2, o);
    __syncthreads();
    if ((tid & 31) == 0) red[tid >> 5] = s2;
    __syncthreads();
    float tot2 = red[0]+red[1]+red[2]+red[3]+red[4]+red[5]+red[6]+red[7];
    float inv = rsqrtf(tot2 * (1.0f/512.0f) + 1e-5f);
    out[(size_t)row*Cc + tid]       = d0*inv*w[tid]       + b[tid];
    out[(size_t)row*Cc + tid + 256] = d1*inv*w[tid + 256] + b[tid + 256];
}

// ---------------- launch ----------------
extern "C" void kernel_launch(void* const* d_in, const int* in_sizes, int n_in,
                              void* d_out, int out_size) {
    (void)in_sizes; (void)n_in; (void)out_size;
    const float* x         = (const float*)d_in[0];
    const int*   ct        = (const int*)  d_in[1];
    const float* w_attn    = (const float*)d_in[2];
    const float* b_attn    = (const float*)d_in[3];
    const float* w_proj    = (const float*)d_in[4];
    const float* b_proj    = (const float*)d_in[5];
    const float* rpe_table = (const float*)d_in[6];
    const float* ln1_w     = (const float*)d_in[7];
    const float* ln1_b     = (const float*)d_in[8];
    const float* ln2_w     = (const float*)d_in[9];
    const float* ln2_b     = (const float*)d_in[10];
    const float* w_fc      = (const float*)d_in[11];
    const float* b_fc      = (const float*)d_in[12];
    const float* w_fc2     = (const float*)d_in[13];
    const float* b_fc2     = (const float*)d_in[14];
    float* out = (float*)d_out;

    float *y_, *res_, *x1_, *h_, *res2_;
    cudaGetSymbolAddress((void**)&y_,    g_y);
    cudaGetSymbolAddress((void**)&res_,  g_res);
    cudaGetSymbolAddress((void**)&x1_,   g_x1);
    cudaGetSymbolAddress((void**)&h_,    g_h);
    cudaGetSymbolAddress((void**)&res2_, g_res2);

    cudaFuncSetAttribute(attn_kernel, cudaFuncAttributeMaxDynamicSharedMemorySize,
                         (int)sizeof(AttnSmem));

    bucket_kernel<<<(Bb*Tt*Tt + 255)/256, 256>>>(ct);
    sgemm_kernel<0><<<dim3(12, 125), 256>>>(x, w_attn, b_attn, nullptr, nullptr,
                                            Mrows, 3*Cc, Cc);
    attn_kernel<<<dim3(8, Bb*Hh), 256, sizeof(AttnSmem)>>>(rpe_table);
    sgemm_kernel<1><<<dim3(4, 125), 256>>>(y_, w_proj, b_proj, res_, x,
                                           Mrows, Cc, Cc);
    ln_kernel<<<Mrows, 256>>>(res_, ln1_w, ln1_b, x1_);
    sgemm_kernel<2><<<dim3(8, 125), 256>>>(x1_, w_fc, b_fc, h_, nullptr,
                                            Mrows, 2*Cc, Cc);
    sgemm_kernel<3><<<dim3(4, 125), 256>>>(h_, w_fc2, b_fc2, res2_, x1_,
                                           Mrows, Cc, 2*Cc);
    ln_kernel<<<Mrows, 256>>>(res2_, ln2_w, ln2_b, out);
}

// round 5
// speedup vs baseline: 2.0406x; 1.7717x over previous
#include <cuda_runtime.h>
#include <cuda_bf16.h>
#include <math.h>
#include <stdint.h>

#define Bb 32
#define Tt 500
#define Cc 512
#define Hh 8
#define Dd 64
#define Mrows (Bb*Tt)
#define NBUCKETS 49

// ---------------- scratch (static device globals; no allocation) ----------------
__device__ float g_qT[(size_t)Bb*Hh*Dd*Tt];   // [(b*H+h)*D + d][t]
__device__ float g_kT[(size_t)Bb*Hh*Dd*Tt];
__device__ float g_v [(size_t)Bb*Hh*Tt*Dd];
__device__ float g_y [(size_t)Mrows*Cc];
__device__ float g_res [(size_t)Mrows*Cc];
__device__ float g_x1  [(size_t)Mrows*Cc];
__device__ float g_h   [(size_t)Mrows*2*Cc];
__device__ float g_res2[(size_t)Mrows*Cc];
__device__ unsigned char g_bucket[(size_t)Bb*Tt*Tt + 64];

// bf16 split buffers
__device__ __nv_bfloat16 g_ahi[(size_t)Mrows*1024];
__device__ __nv_bfloat16 g_alo[(size_t)Mrows*1024];
__device__ __nv_bfloat16 g_wh_attn[1536*512], g_wl_attn[1536*512];
__device__ __nv_bfloat16 g_wh_proj[512*512],  g_wl_proj[512*512];
__device__ __nv_bfloat16 g_wh_fc[1024*512],   g_wl_fc[1024*512];
__device__ __nv_bfloat16 g_wh_fc2[512*1024],  g_wl_fc2[512*1024];

// ---------------- helpers ----------------
__device__ __forceinline__ uint32_t smem_u32(const void* p) {
    uint32_t a;
    asm("{ .reg .u64 t; cvta.to.shared.u64 t, %1; cvt.u32.u64 %0, t; }" : "=r"(a) : "l"(p));
    return a;
}
__device__ __forceinline__ uint32_t swz128(uint32_t o) { return o ^ ((o >> 3) & 0x70); }

__device__ __forceinline__ void cp16(uint32_t dst, const void* src) {
    asm volatile("cp.async.cg.shared.global [%0], [%1], 16;" :: "r"(dst), "l"(src));
}
__device__ __forceinline__ void cp_commit() {
    asm volatile("cp.async.commit_group;" ::: "memory");
}
template<int N> __device__ __forceinline__ void cp_wait() {
    asm volatile("cp.async.wait_group %0;" :: "n"(N) : "memory");
}

#define LDSM4(r, addr) \
    asm volatile("ldmatrix.sync.aligned.m8n8.x4.shared.b16 {%0,%1,%2,%3}, [%4];" \
        : "=r"((r)[0]),"=r"((r)[1]),"=r"((r)[2]),"=r"((r)[3]) : "r"(addr))

#define MMA16816(d, a, b0, b1) \
    asm volatile("mma.sync.aligned.m16n8k16.row.col.f32.bf16.bf16.f32 " \
        "{%0,%1,%2,%3}, {%4,%5,%6,%7}, {%8,%9}, {%0,%1,%2,%3};" \
        : "+f"((d)[0]),"+f"((d)[1]),"+f"((d)[2]),"+f"((d)[3]) \
        : "r"((a)[0]),"r"((a)[1]),"r"((a)[2]),"r"((a)[3]), "r"(b0),"r"(b1))

// ---------------- bucket ids ----------------
__global__ void __launch_bounds__(256) bucket_kernel(const int* __restrict__ ct) {
    int i = blockIdx.x * blockDim.x + threadIdx.x;
    if (i >= Bb*Tt*Tt) return;
    int b = i / (Tt*Tt);
    int r = i - b*(Tt*Tt);
    int t = r / Tt;
    int s = r - t*Tt;
    int2 c1 = ((const int2*)ct)[b*Tt + t];
    int2 c2 = ((const int2*)ct)[b*Tt + s];
    int dx = c1.x - c2.x, dy = c1.y - c2.y;
    float dist = sqrtf((float)(dx*dx + dy*dy));
    float rel = truncf(dist / 12.0f);
    float idx;
    if (rel <= 12.0f) idx = rel;
    else idx = fminf(rintf(12.0f + logf(rel / 12.0f) * 5.7707801635558523f), 24.0f);
    g_bucket[i] = (unsigned char)(int)(idx + 24.0f);
}

// ---------------- bf16 split conversions ----------------
__global__ void __launch_bounds__(256) aconv_kernel(const float4* __restrict__ in,
    uint2* __restrict__ hi, uint2* __restrict__ lo, int n4)
{
    int i = blockIdx.x * blockDim.x + threadIdx.x;
    if (i >= n4) return;
    float4 f = in[i];
    __nv_bfloat16 h0 = __float2bfloat16(f.x), h1 = __float2bfloat16(f.y);
    __nv_bfloat16 h2 = __float2bfloat16(f.z), h3 = __float2bfloat16(f.w);
    __nv_bfloat16 l0 = __float2bfloat16(f.x - __bfloat162float(h0));
    __nv_bfloat16 l1 = __float2bfloat16(f.y - __bfloat162float(h1));
    __nv_bfloat16 l2 = __float2bfloat16(f.z - __bfloat162float(h2));
    __nv_bfloat16 l3 = __float2bfloat16(f.w - __bfloat162float(h3));
    uint2 ho, lv;
    ho.x = (uint32_t)__bfloat16_as_ushort(h0) | ((uint32_t)__bfloat16_as_ushort(h1) << 16);
    ho.y = (uint32_t)__bfloat16_as_ushort(h2) | ((uint32_t)__bfloat16_as_ushort(h3) << 16);
    lv.x = (uint32_t)__bfloat16_as_ushort(l0) | ((uint32_t)__bfloat16_as_ushort(l1) << 16);
    lv.y = (uint32_t)__bfloat16_as_ushort(l2) | ((uint32_t)__bfloat16_as_ushort(l3) << 16);
    hi[i] = ho; lo[i] = lv;
}

// W [K,N] fp32 -> WT [N,K] bf16 hi/lo
__global__ void __launch_bounds__(256) wconv_kernel(const float* __restrict__ W,
    __nv_bfloat16* __restrict__ hi, __nv_bfloat16* __restrict__ lo, int K, int N)
{
    __shared__ float tile[32][33];
    int nb = blockIdx.x << 5, kb = blockIdx.y << 5;
    int tx = threadIdx.x & 31, ty = threadIdx.x >> 5;
#pragma unroll
    for (int i = 0; i < 32; i += 8)
        tile[ty + i][tx] = W[(size_t)(kb + ty + i)*N + nb + tx];
    __syncthreads();
#pragma unroll
    for (int i = 0; i < 32; i += 8) {
        float f = tile[tx][ty + i];
        __nv_bfloat16 h_ = __float2bfloat16(f);
        __nv_bfloat16 l_ = __float2bfloat16(f - __bfloat162float(h_));
        size_t o = (size_t)(nb + ty + i)*K + kb + tx;
        hi[o] = h_; lo[o] = l_;
    }
}

// ---------------- mma.sync GEMM: CTA 128x128, KC=64, split bf16, cp.async 2-stage ----
#define TILE_B   16384
#define BUF_B    65536          // Ahi,Alo,Bhi,Blo each 16KB
#define GSM_TOT  131072
// MODE 0: qkv scatter   MODE 1/3: +resid   MODE 2: gelu
template<int MODE>
__global__ void __launch_bounds__(256) mma_gemm(
    const __nv_bfloat16* __restrict__ Ahi, const __nv_bfloat16* __restrict__ Alo,
    const __nv_bfloat16* __restrict__ Bhi, const __nv_bfloat16* __restrict__ Blo,
    const float* __restrict__ bias, float* __restrict__ Cout,
    const float* __restrict__ resid, int M, int N, int K)
{
    extern __shared__ char smraw[];
    const uint32_t sb = smem_u32(smraw);
    const int tid = threadIdx.x;
    const int wid = tid >> 5, lane = tid & 31;
    const int wm = wid & 3, wn = wid >> 2;
    const int m0 = blockIdx.y << 7, n0 = blockIdx.x << 7;

    const int ldr = tid >> 3, ldu = tid & 7;  // cp.async: 32 rows per pass x 8 16B-units

    auto issue = [&](int kc, int buf) {
        uint32_t base = sb + buf*BUF_B;
#pragma unroll
        for (int p = 0; p < 4; p++) {
            int row = ldr + (p << 5);
            uint32_t d = swz128((uint32_t)(row << 7) + (ldu << 4));
            size_t ao = (size_t)(m0 + row)*K + kc + (ldu << 3);
            size_t bo = (size_t)(n0 + row)*K + kc + (ldu << 3);
            cp16(base + d,            Ahi + ao);
            cp16(base + TILE_B + d,   Alo + ao);
            cp16(base + 2*TILE_B + d, Bhi + bo);
            cp16(base + 3*TILE_B + d, Blo + bo);
        }
        cp_commit();
    };

    float acc[2][8][4] = {};

    // ldmatrix address components
    const int grp = lane >> 3, rim = lane & 7;
    const int arow0 = (wm << 5) + ((grp & 1) << 3) + rim;   // + mt*16
    const int aku0  = grp >> 1;                             // + ks*2
    const int brow0 = (wn << 6) + ((grp >> 1) << 3) + rim;  // + np*16
    const int bku0  = grp & 1;

    issue(0, 0);
    const int nch = K >> 6;
    for (int c = 0; c < nch; c++) {
        if (c + 1 < nch) { issue((c + 1) << 6, (c + 1) & 1); cp_wait<1>(); }
        else             { cp_wait<0>(); }
        __syncthreads();
        const uint32_t base = sb + (c & 1)*BUF_B;
#pragma unroll
        for (int ks = 0; ks < 4; ks++) {
            uint32_t ah[2][4], al[2][4];
#pragma unroll
            for (int mt = 0; mt < 2; mt++) {
                uint32_t off = swz128((uint32_t)((arow0 + (mt << 4)) << 7) + ((aku0 + (ks << 1)) << 4));
                LDSM4(ah[mt], base + off);
                LDSM4(al[mt], base + TILE_B + off);
            }
            uint32_t bh[4][4], bl[4][4];
#pragma unroll
            for (int np = 0; np < 4; np++) {
                uint32_t off = swz128((uint32_t)((brow0 + (np << 4)) << 7) + ((bku0 + (ks << 1)) << 4));
                LDSM4(bh[np], base + 2*TILE_B + off);
                LDSM4(bl[np], base + 3*TILE_B + off);
            }
#pragma unroll
            for (int mt = 0; mt < 2; mt++)
#pragma unroll
                for (int nt = 0; nt < 8; nt++) {
                    const uint32_t* fh = &bh[nt >> 1][(nt & 1) << 1];
                    const uint32_t* fl = &bl[nt >> 1][(nt & 1) << 1];
                    MMA16816(acc[mt][nt], ah[mt], fh[0], fh[1]);
                    MMA16816(acc[mt][nt], ah[mt], fl[0], fl[1]);
                    MMA16816(acc[mt][nt], al[mt], fh[0], fh[1]);
                }
        }
        __syncthreads();
    }

    // epilogue
#pragma unroll
    for (int mt = 0; mt < 2; mt++) {
#pragma unroll
        for (int half = 0; half < 2; half++) {
            int mrow = m0 + (wm << 5) + (mt << 4) + (half << 3) + (lane >> 2);
            int b_ = mrow / Tt, t = mrow - b_*Tt;
#pragma unroll
            for (int nt = 0; nt < 8; nt++) {
                int cix = n0 + (wn << 6) + (nt << 3) + ((lane & 3) << 1);
                float v0 = acc[mt][nt][half*2 + 0] + bias[cix];
                float v1 = acc[mt][nt][half*2 + 1] + bias[cix + 1];
                if (MODE == 0) {
#pragma unroll
                    for (int u = 0; u < 2; u++) {
                        int c = cix + u;
                        float v = u ? v1 : v0;
                        int sec = c >> 9, cc2 = c & 511, hh = cc2 >> 6, d = cc2 & 63;
                        int bh_ = b_*Hh + hh;
                        if (sec == 0)      g_qT[((size_t)bh_*Dd + d)*Tt + t] = v;
                        else if (sec == 1) g_kT[((size_t)bh_*Dd + d)*Tt + t] = v;
                        else               g_v [((size_t)bh_*Tt + t)*Dd + d] = v;
                    }
                } else if (MODE == 2) {
                    v0 = 0.5f * v0 * (1.0f + erff(v0 * 0.7071067811865475f));
                    v1 = 0.5f * v1 * (1.0f + erff(v1 * 0.7071067811865475f));
                    float2 o; o.x = v0; o.y = v1;
                    *(float2*)(Cout + (size_t)mrow*N + cix) = o;
                } else {
                    float2 r = *(const float2*)(resid + (size_t)mrow*N + cix);
                    float2 o; o.x = v0 + r.x; o.y = v1 + r.y;
                    *(float2*)(Cout + (size_t)mrow*N + cix) = o;
                }
            }
        }
    }
}

// ---------------- fused flash attention with RPE bias ----------------
struct AttnSmem {
    float Qst[Dd][64];
    float Kst[Dd][64];
    float Vs [64][Dd];
    float Ps [64][65];
    float row_m[64], row_l[64], row_scale[64];
    float rpe[64];
    unsigned char bk[64][64];
};

__global__ void __launch_bounds__(256) attn_kernel(const float* __restrict__ rpe_table) {
    extern __shared__ char smraw[];
    AttnSmem& sm = *reinterpret_cast<AttnSmem*>(smraw);
    const int tid = threadIdx.x;
    const int tx = tid & 15, ty = tid >> 4;
    const int qt = blockIdx.x;
    const int bh = blockIdx.y;
    const int b_ = bh >> 3, h = bh & 7;
    const int hp = bh >> 5, bp = bh & 31;
    const int t0 = qt << 6;

    if (tid < NBUCKETS) sm.rpe[tid] = rpe_table[hp*NBUCKETS + tid];
    if (tid < 64) { sm.row_m[tid] = -INFINITY; sm.row_l[tid] = 0.0f; }

    {
        const float* qb = g_qT + (size_t)bh*Dd*Tt;
#pragma unroll
        for (int it = 0; it < 4; it++) {
            int f = tid + it*256;
            int d = f >> 4;
            int r4 = (f & 15) << 2;
            float4 v = make_float4(0.f,0.f,0.f,0.f);
            const float* p = qb + (size_t)d*Tt;
            if (t0 + r4 + 3 < Tt) v = *(const float4*)(p + t0 + r4);
            else {
                if (t0+r4+0 < Tt) v.x = p[t0+r4+0];
                if (t0+r4+1 < Tt) v.y = p[t0+r4+1];
                if (t0+r4+2 < Tt) v.z = p[t0+r4+2];
                if (t0+r4+3 < Tt) v.w = p[t0+r4+3];
            }
            *(float4*)&sm.Qst[d][r4] = v;
        }
    }

    float O[4][4] = {};
    const float* kb = g_kT + (size_t)bh*Dd*Tt;
    const float* vb = g_v  + (size_t)bh*Tt*Dd;
    const unsigned char* bkb = g_bucket + (size_t)bp*Tt*Tt;

    for (int s0 = 0; s0 < Tt; s0 += 64) {
        __syncthreads();
#pragma unroll
        for (int it = 0; it < 4; it++) {
            int f = tid + it*256;
            int d = f >> 4;
            int c4 = (f & 15) << 2;
            float4 v = make_float4(0.f,0.f,0.f,0.f);
            const float* p = kb + (size_t)d*Tt;
            if (s0 + c4 + 3 < Tt) v = *(const float4*)(p + s0 + c4);
            else {
                if (s0+c4+0 < Tt) v.x = p[s0+c4+0];
                if (s0+c4+1 < Tt) v.y = p[s0+c4+1];
                if (s0+c4+2 < Tt) v.z = p[s0+c4+2];
                if (s0+c4+3 < Tt) v.w = p[s0+c4+3];
            }
            *(float4*)&sm.Kst[d][c4] = v;
        }
#pragma unroll
        for (int it = 0; it < 4; it++) {
            int f = tid + it*256;
            int c = f >> 4;
            int d4 = (f & 15) << 2;
            float4 v = make_float4(0.f,0.f,0.f,0.f);
            if (s0 + c < Tt) v = *(const float4*)(vb + (size_t)(s0 + c)*Dd + d4);
            *(float4*)&sm.Vs[c][d4] = v;
        }
#pragma unroll
        for (int it = 0; it < 4; it++) {
            int f = tid + it*256;
            int r = f >> 4;
            int c4 = (f & 15) << 2;
            uchar4 u4 = make_uchar4(0,0,0,0);
            if (t0 + r < Tt && s0 + c4 < Tt)
                u4 = *(const uchar4*)(bkb + (size_t)(t0 + r)*Tt + s0 + c4);
            *(uchar4*)&sm.bk[r][c4] = u4;
        }
        __syncthreads();

        float acc[4][4] = {};
#pragma unroll
        for (int k = 0; k < Dd; k++) {
            float4 a  = *(const float4*)&sm.Qst[k][ty << 2];
            float4 bb = *(const float4*)&sm.Kst[k][tx << 2];
            float av_[4] = {a.x, a.y, a.z, a.w};
            float bv_[4] = {bb.x, bb.y, bb.z, bb.w};
#pragma unroll
            for (int i = 0; i < 4; i++)
#pragma unroll
                for (int j = 0; j < 4; j++)
                    acc[i][j] += av_[i] * bv_[j];
        }
#pragma unroll
        for (int i = 0; i < 4; i++) {
            int r = (ty << 2) + i;
#pragma unroll
            for (int j = 0; j < 4; j++) {
                int c = (tx << 2) + j;
                float sS = acc[i][j] * 0.125f + sm.rpe[sm.bk[r][c]];
                if (s0 + c >= Tt) sS = -INFINITY;
                sm.Ps[r][c] = sS;
            }
        }
        __syncthreads();

        {
            int r = tid >> 2, qq = tid & 3;
            int cbase = qq << 4;
            float mx = -INFINITY;
#pragma unroll
            for (int u = 0; u < 16; u++) mx = fmaxf(mx, sm.Ps[r][cbase+u]);
            mx = fmaxf(mx, __shfl_xor_sync(0xffffffffu, mx, 1));
            mx = fmaxf(mx, __shfl_xor_sync(0xffffffffu, mx, 2));
            float m_old = sm.row_m[r];
            float m_new = fmaxf(m_old, mx);
            float ssum = 0.f;
#pragma unroll
            for (int u = 0; u < 16; u++) {
                float p = __expf(sm.Ps[r][cbase+u] - m_new);
                sm.Ps[r][cbase+u] = p;
                ssum += p;
            }
            ssum += __shfl_xor_sync(0xffffffffu, ssum, 1);
            ssum += __shfl_xor_sync(0xffffffffu, ssum, 2);
            if (qq == 0) {
                float sc = __expf(m_old - m_new);
                sm.row_scale[r] = sc;
                sm.row_l[r] = sm.row_l[r]*sc + ssum;
                sm.row_m[r] = m_new;
            }
        }
        __syncthreads();

        {
            float sc[4];
#pragma unroll
            for (int i = 0; i < 4; i++) sc[i] = sm.row_scale[(ty<<2)+i];
#pragma unroll
            for (int i = 0; i < 4; i++)
#pragma unroll
                for (int j = 0; j < 4; j++) O[i][j] *= sc[i];
#pragma unroll
            for (int c = 0; c < 64; c++) {
                float4 v = *(const float4*)&sm.Vs[c][tx << 2];
                float vv[4] = {v.x, v.y, v.z, v.w};
#pragma unroll
                for (int i = 0; i < 4; i++) {
                    float p = sm.Ps[(ty<<2)+i][c];
#pragma unroll
                    for (int j = 0; j < 4; j++) O[i][j] += p * vv[j];
                }
            }
        }
    }

#pragma unroll
    for (int i = 0; i < 4; i++) {
        int r = (ty << 2) + i;
        int t = t0 + r;
        if (t < Tt) {
            float inv = 1.0f / sm.row_l[r];
            float4 o;
            o.x = O[i][0]*inv; o.y = O[i][1]*inv; o.z = O[i][2]*inv; o.w = O[i][3]*inv;
            *(float4*)&g_y[((size_t)(b_*Tt + t))*Cc + h*Dd + (tx << 2)] = o;
        }
    }
}

// ---------------- layernorm ----------------
__global__ void __launch_bounds__(256) ln_kernel(const float* __restrict__ in,
    const float* __restrict__ w, const float* __restrict__ b, float* __restrict__ out)
{
    __shared__ float red[8];
    int row = blockIdx.x;
    const float* x = in + (size_t)row*Cc;
    int tid = threadIdx.x;
    float v0 = x[tid], v1 = x[tid + 256];
    float s = v0 + v1;
#pragma unroll
    for (int o = 16; o > 0; o >>= 1) s += __shfl_xor_sync(0xffffffffu, s, o);
    if ((tid & 31) == 0) red[tid >> 5] = s;
    __syncthreads();
    float tot = red[0]+red[1]+red[2]+red[3]+red[4]+red[5]+red[6]+red[7];
    float mean = tot * (1.0f/512.0f);
    float d0 = v0 - mean, d1 = v1 - mean;
    float s2 = d0*d0 + d1*d1;
#pragma unroll
    for (int o = 16; o > 0; o >>= 1) s2 += __shfl_xor_sync(0xffffffffu, s2, o);
    __syncthreads();
    if ((tid & 31) == 0) red[tid >> 5] = s2;
    __syncthreads();
    float tot2 = red[0]+red[1]+red[2]+red[3]+red[4]+red[5]+red[6]+red[7];
    float inv = rsqrtf(tot2 * (1.0f/512.0f) + 1e-5f);
    out[(size_t)row*Cc + tid]       = d0*inv*w[tid]       + b[tid];
    out[(size_t)row*Cc + tid + 256] = d1*inv*w[tid + 256] + b[tid + 256];
}

// ---------------- launch ----------------
extern "C" void kernel_launch(void* const* d_in, const int* in_sizes, int n_in,
                              void* d_out, int out_size) {
    (void)in_sizes; (void)n_in; (void)out_size;
    const float* x         = (const float*)d_in[0];
    const int*   ct        = (const int*)  d_in[1];
    const float* w_attn    = (const float*)d_in[2];
    const float* b_attn    = (const float*)d_in[3];
    const float* w_proj    = (const float*)d_in[4];
    const float* b_proj    = (const float*)d_in[5];
    const float* rpe_table = (const float*)d_in[6];
    const float* ln1_w     = (const float*)d_in[7];
    const float* ln1_b     = (const float*)d_in[8];
    const float* ln2_w     = (const float*)d_in[9];
    const float* ln2_b     = (const float*)d_in[10];
    const float* w_fc      = (const float*)d_in[11];
    const float* b_fc      = (const float*)d_in[12];
    const float* w_fc2     = (const float*)d_in[13];
    const float* b_fc2     = (const float*)d_in[14];
    float* out = (float*)d_out;

    float *y_, *res_, *x1_, *h_, *res2_;
    cudaGetSymbolAddress((void**)&y_,    g_y);
    cudaGetSymbolAddress((void**)&res_,  g_res);
    cudaGetSymbolAddress((void**)&x1_,   g_x1);
    cudaGetSymbolAddress((void**)&h_,    g_h);
    cudaGetSymbolAddress((void**)&res2_, g_res2);
    __nv_bfloat16 *ahi, *alo, *wha, *wla, *whp, *wlp, *whf, *wlf, *whf2, *wlf2;
    cudaGetSymbolAddress((void**)&ahi,  g_ahi);
    cudaGetSymbolAddress((void**)&alo,  g_alo);
    cudaGetSymbolAddress((void**)&wha,  g_wh_attn);
    cudaGetSymbolAddress((void**)&wla,  g_wl_attn);
    cudaGetSymbolAddress((void**)&whp,  g_wh_proj);
    cudaGetSymbolAddress((void**)&wlp,  g_wl_proj);
    cudaGetSymbolAddress((void**)&whf,  g_wh_fc);
    cudaGetSymbolAddress((void**)&wlf,  g_wl_fc);
    cudaGetSymbolAddress((void**)&whf2, g_wh_fc2);
    cudaGetSymbolAddress((void**)&wlf2, g_wl_fc2);

    cudaFuncSetAttribute(attn_kernel, cudaFuncAttributeMaxDynamicSharedMemorySize,
                         (int)sizeof(AttnSmem));
    cudaFuncSetAttribute(mma_gemm<0>, cudaFuncAttributeMaxDynamicSharedMemorySize, GSM_TOT);
    cudaFuncSetAttribute(mma_gemm<1>, cudaFuncAttributeMaxDynamicSharedMemorySize, GSM_TOT);
    cudaFuncSetAttribute(mma_gemm<2>, cudaFuncAttributeMaxDynamicSharedMemorySize, GSM_TOT);
    cudaFuncSetAttribute(mma_gemm<3>, cudaFuncAttributeMaxDynamicSharedMemorySize, GSM_TOT);

    bucket_kernel<<<(Bb*Tt*Tt + 255)/256, 256>>>(ct);

    // weight transpose + split
    wconv_kernel<<<dim3(1536/32, 512/32), 256>>>(w_attn, wha, wla, 512, 1536);
    wconv_kernel<<<dim3(512/32, 512/32),  256>>>(w_proj, whp, wlp, 512, 512);
    wconv_kernel<<<dim3(1024/32, 512/32), 256>>>(w_fc,   whf, wlf, 512, 1024);
    wconv_kernel<<<dim3(512/32, 1024/32), 256>>>(w_fc2,  whf2, wlf2, 1024, 512);

    // qkv
    aconv_kernel<<<(Mrows*Cc/4 + 255)/256, 256>>>((const float4*)x, (uint2*)ahi, (uint2*)alo, Mrows*Cc/4);
    mma_gemm<0><<<dim3(12, 125), 256, GSM_TOT>>>(ahi, alo, wha, wla, b_attn,
                                                 nullptr, nullptr, Mrows, 3*Cc, Cc);
    attn_kernel<<<dim3(8, Bb*Hh), 256, sizeof(AttnSmem)>>>(rpe_table);

    // proj + resid
    aconv_kernel<<<(Mrows*Cc/4 + 255)/256, 256>>>((const float4*)y_, (uint2*)ahi, (uint2*)alo, Mrows*Cc/4);
    mma_gemm<1><<<dim3(4, 125), 256, GSM_TOT>>>(ahi, alo, whp, wlp, b_proj,
                                                res_, x, Mrows, Cc, Cc);
    ln_kernel<<<Mrows, 256>>>(res_, ln1_w, ln1_b, x1_);

    // fc + gelu
    aconv_kernel<<<(Mrows*Cc/4 + 255)/256, 256>>>((const float4*)x1_, (uint2*)ahi, (uint2*)alo, Mrows*Cc/4);
    mma_gemm<2><<<dim3(8, 125), 256, GSM_TOT>>>(ahi, alo, whf, wlf, b_fc,
                                                h_, nullptr, Mrows, 2*Cc, Cc);

    // fc2 + resid
    aconv_kernel<<<(Mrows*2*Cc/4 + 255)/256, 256>>>((const float4*)h_, (uint2*)ahi, (uint2*)alo, Mrows*2*Cc/4);
    mma_gemm<3><<<dim3(4, 125), 256, GSM_TOT>>>(ahi, alo, whf2, wlf2, b_fc2,
                                                res2_, x1_, Mrows, Cc, 2*Cc);
    ln_kernel<<<Mrows, 256>>>(res2_, ln2_w, ln2_b, out);
}

// round 6
// speedup vs baseline: 2.4510x; 1.2011x over previous
#include <cuda_runtime.h>
#include <cuda_bf16.h>
#include <math.h>
#include <stdint.h>

#define Bb 32
#define Tt 500
#define Cc 512
#define Hh 8
#define Dd 64
#define Mrows (Bb*Tt)
#define NBUCKETS 49

// ---------------- scratch (static device globals; zero-initialized) ----------------
__device__ float g_res [(size_t)Mrows*Cc];
__device__ float g_x1  [(size_t)Mrows*Cc];
__device__ float g_res2[(size_t)Mrows*Cc];
__device__ unsigned char g_bucket[(size_t)Bb*Tt*Tt + 64];

// bf16 split buffers (padded; pad region stays zero)
__device__ __nv_bfloat16 g_qh[(size_t)(Bb*Hh*Tt + 64)*Dd], g_ql[(size_t)(Bb*Hh*Tt + 64)*Dd];
__device__ __nv_bfloat16 g_kh[(size_t)(Bb*Hh*Tt + 64)*Dd], g_kl[(size_t)(Bb*Hh*Tt + 64)*Dd];
__device__ __nv_bfloat16 g_vth[(size_t)Bb*Hh*Dd*512 + 1024], g_vtl[(size_t)Bb*Hh*Dd*512 + 1024];
__device__ __nv_bfloat16 g_ahi[(size_t)Mrows*1024 + 1024], g_alo[(size_t)Mrows*1024 + 1024];
__device__ __nv_bfloat16 g_bhi[(size_t)Mrows*1024 + 1024], g_blo[(size_t)Mrows*1024 + 1024];
__device__ __nv_bfloat16 g_wh_attn[1536*512], g_wl_attn[1536*512];
__device__ __nv_bfloat16 g_wh_proj[512*512],  g_wl_proj[512*512];
__device__ __nv_bfloat16 g_wh_fc[1024*512],   g_wl_fc[1024*512];
__device__ __nv_bfloat16 g_wh_fc2[512*1024],  g_wl_fc2[512*1024];

// ---------------- helpers ----------------
__device__ __forceinline__ uint32_t smem_u32(const void* p) {
    uint32_t a;
    asm("{ .reg .u64 t; cvta.to.shared.u64 t, %1; cvt.u32.u64 %0, t; }" : "=r"(a) : "l"(p));
    return a;
}
__device__ __forceinline__ uint32_t swz128(uint32_t o) { return o ^ ((o >> 3) & 0x70); }

__device__ __forceinline__ void cp16(uint32_t dst, const void* src) {
    asm volatile("cp.async.cg.shared.global [%0], [%1], 16;" :: "r"(dst), "l"(src));
}
__device__ __forceinline__ void cp_commit() {
    asm volatile("cp.async.commit_group;" ::: "memory");
}
template<int N> __device__ __forceinline__ void cp_wait() {
    asm volatile("cp.async.wait_group %0;" :: "n"(N) : "memory");
}

#define LDSM4(r, addr) \
    asm volatile("ldmatrix.sync.aligned.m8n8.x4.shared.b16 {%0,%1,%2,%3}, [%4];" \
        : "=r"((r)[0]),"=r"((r)[1]),"=r"((r)[2]),"=r"((r)[3]) : "r"(addr))

#define MMA16816(d, a, b0, b1) \
    asm volatile("mma.sync.aligned.m16n8k16.row.col.f32.bf16.bf16.f32 " \
        "{%0,%1,%2,%3}, {%4,%5,%6,%7}, {%8,%9}, {%0,%1,%2,%3};" \
        : "+f"((d)[0]),"+f"((d)[1]),"+f"((d)[2]),"+f"((d)[3]) \
        : "r"((a)[0]),"r"((a)[1]),"r"((a)[2]),"r"((a)[3]), "r"(b0),"r"(b1))

__device__ __forceinline__ void split_bf16(float v, unsigned short& h, unsigned short& l) {
    __nv_bfloat16 hb = __float2bfloat16(v);
    __nv_bfloat16 lb = __float2bfloat16(v - __bfloat162float(hb));
    h = __bfloat16_as_ushort(hb);
    l = __bfloat16_as_ushort(lb);
}

// ---------------- bucket ids ----------------
__global__ void __launch_bounds__(256) bucket_kernel(const int* __restrict__ ct) {
    int i = blockIdx.x * blockDim.x + threadIdx.x;
    if (i >= Bb*Tt*Tt) return;
    int b = i / (Tt*Tt);
    int r = i - b*(Tt*Tt);
    int t = r / Tt;
    int s = r - t*Tt;
    int2 c1 = ((const int2*)ct)[b*Tt + t];
    int2 c2 = ((const int2*)ct)[b*Tt + s];
    int dx = c1.x - c2.x, dy = c1.y - c2.y;
    float dist = sqrtf((float)(dx*dx + dy*dy));
    float rel = truncf(dist / 12.0f);
    float idx;
    if (rel <= 12.0f) idx = rel;
    else idx = fminf(rintf(12.0f + logf(rel / 12.0f) * 5.7707801635558523f), 24.0f);
    g_bucket[i] = (unsigned char)(int)(idx + 24.0f);
}

// ---------------- bf16 split conversions ----------------
__global__ void __launch_bounds__(256) aconv_kernel(const float4* __restrict__ in,
    uint2* __restrict__ hi, uint2* __restrict__ lo, int n4)
{
    int i = blockIdx.x * blockDim.x + threadIdx.x;
    if (i >= n4) return;
    float4 f = in[i];
    unsigned short h0,h1,h2,h3,l0,l1,l2,l3;
    split_bf16(f.x, h0, l0); split_bf16(f.y, h1, l1);
    split_bf16(f.z, h2, l2); split_bf16(f.w, h3, l3);
    uint2 ho, lv;
    ho.x = (uint32_t)h0 | ((uint32_t)h1 << 16);
    ho.y = (uint32_t)h2 | ((uint32_t)h3 << 16);
    lv.x = (uint32_t)l0 | ((uint32_t)l1 << 16);
    lv.y = (uint32_t)l2 | ((uint32_t)l3 << 16);
    hi[i] = ho; lo[i] = lv;
}

// W [K,N] fp32 -> WT [N,K] bf16 hi/lo
__global__ void __launch_bounds__(256) wconv_kernel(const float* __restrict__ W,
    __nv_bfloat16* __restrict__ hi, __nv_bfloat16* __restrict__ lo, int K, int N)
{
    __shared__ float tile[32][33];
    int nb = blockIdx.x << 5, kb = blockIdx.y << 5;
    int tx = threadIdx.x & 31, ty = threadIdx.x >> 5;
#pragma unroll
    for (int i = 0; i < 32; i += 8)
        tile[ty + i][tx] = W[(size_t)(kb + ty + i)*N + nb + tx];
    __syncthreads();
#pragma unroll
    for (int i = 0; i < 32; i += 8) {
        float f = tile[tx][ty + i];
        unsigned short h_, l_;
        split_bf16(f, h_, l_);
        size_t o = (size_t)(nb + ty + i)*K + kb + tx;
        hi[o] = __ushort_as_bfloat16(h_); lo[o] = __ushort_as_bfloat16(l_);
    }
}

// ---------------- mma.sync GEMM: CTA 128x128, KC=64, split bf16, cp.async 2-stage ----
#define TILE_B   16384
#define BUF_B    65536
#define GSM_TOT  131072
// MODE 0: qkv split-scatter  MODE 1/3: fp32 out = val + resid  MODE 2: gelu -> split out
template<int MODE>
__global__ void __launch_bounds__(256) mma_gemm(
    const __nv_bfloat16* __restrict__ Ahi, const __nv_bfloat16* __restrict__ Alo,
    const __nv_bfloat16* __restrict__ Bhi, const __nv_bfloat16* __restrict__ Blo,
    const float* __restrict__ bias, float* __restrict__ Cout,
    const float* __restrict__ resid,
    __nv_bfloat16* __restrict__ Shi, __nv_bfloat16* __restrict__ Slo,
    int M, int N, int K)
{
    extern __shared__ char smraw[];
    const uint32_t sb = smem_u32(smraw);
    const int tid = threadIdx.x;
    const int wid = tid >> 5, lane = tid & 31;
    const int wm = wid & 3, wn = wid >> 2;
    const int m0 = blockIdx.y << 7, n0 = blockIdx.x << 7;

    const int ldr = tid >> 3, ldu = tid & 7;

    auto issue = [&](int kc, int buf) {
        uint32_t base = sb + buf*BUF_B;
#pragma unroll
        for (int p = 0; p < 4; p++) {
            int row = ldr + (p << 5);
            uint32_t d = swz128((uint32_t)(row << 7) + (ldu << 4));
            size_t ao = (size_t)(m0 + row)*K + kc + (ldu << 3);
            size_t bo = (size_t)(n0 + row)*K + kc + (ldu << 3);
            cp16(base + d,            Ahi + ao);
            cp16(base + TILE_B + d,   Alo + ao);
            cp16(base + 2*TILE_B + d, Bhi + bo);
            cp16(base + 3*TILE_B + d, Blo + bo);
        }
        cp_commit();
    };

    float acc[2][8][4] = {};

    const int grp = lane >> 3, rim = lane & 7;
    const int arow0 = (wm << 5) + ((grp & 1) << 3) + rim;
    const int aku0  = grp >> 1;
    const int brow0 = (wn << 6) + ((grp >> 1) << 3) + rim;
    const int bku0  = grp & 1;

    issue(0, 0);
    const int nch = K >> 6;
    for (int c = 0; c < nch; c++) {
        if (c + 1 < nch) { issue((c + 1) << 6, (c + 1) & 1); cp_wait<1>(); }
        else             { cp_wait<0>(); }
        __syncthreads();
        const uint32_t base = sb + (c & 1)*BUF_B;
#pragma unroll
        for (int ks = 0; ks < 4; ks++) {
            uint32_t ah[2][4], al[2][4];
#pragma unroll
            for (int mt = 0; mt < 2; mt++) {
                uint32_t off = swz128((uint32_t)((arow0 + (mt << 4)) << 7) + ((aku0 + (ks << 1)) << 4));
                LDSM4(ah[mt], base + off);
                LDSM4(al[mt], base + TILE_B + off);
            }
            uint32_t bh[4][4], bl[4][4];
#pragma unroll
            for (int np = 0; np < 4; np++) {
                uint32_t off = swz128((uint32_t)((brow0 + (np << 4)) << 7) + ((bku0 + (ks << 1)) << 4));
                LDSM4(bh[np], base + 2*TILE_B + off);
                LDSM4(bl[np], base + 3*TILE_B + off);
            }
#pragma unroll
            for (int mt = 0; mt < 2; mt++)
#pragma unroll
                for (int nt = 0; nt < 8; nt++) {
                    const uint32_t* fh = &bh[nt >> 1][(nt & 1) << 1];
                    const uint32_t* fl = &bl[nt >> 1][(nt & 1) << 1];
                    MMA16816(acc[mt][nt], ah[mt], fh[0], fh[1]);
                    MMA16816(acc[mt][nt], ah[mt], fl[0], fl[1]);
                    MMA16816(acc[mt][nt], al[mt], fh[0], fh[1]);
                }
        }
        __syncthreads();
    }

    // epilogue
#pragma unroll
    for (int mt = 0; mt < 2; mt++) {
#pragma unroll
        for (int half = 0; half < 2; half++) {
            int mrow = m0 + (wm << 5) + (mt << 4) + (half << 3) + (lane >> 2);
            int b_ = mrow / Tt, t = mrow - b_*Tt;
#pragma unroll
            for (int nt = 0; nt < 8; nt++) {
                int cix = n0 + (wn << 6) + (nt << 3) + ((lane & 3) << 1);
                float v0 = acc[mt][nt][half*2 + 0] + bias[cix];
                float v1 = acc[mt][nt][half*2 + 1] + bias[cix + 1];
                if (MODE == 0) {
                    unsigned short h0,l0,h1,l1;
                    split_bf16(v0, h0, l0); split_bf16(v1, h1, l1);
                    int sec = cix >> 9, cc2 = cix & 511, hh = cc2 >> 6, d = cc2 & 63;
                    int bh_ = b_*Hh + hh;
                    if (sec == 2) {
                        size_t r0i = ((size_t)(bh_*Dd + d))*512 + t;
                        size_t r1i = ((size_t)(bh_*Dd + d + 1))*512 + t;
                        g_vth[r0i] = __ushort_as_bfloat16(h0);
                        g_vth[r1i] = __ushort_as_bfloat16(h1);
                        g_vtl[r0i] = __ushort_as_bfloat16(l0);
                        g_vtl[r1i] = __ushort_as_bfloat16(l1);
                    } else {
                        size_t idx = ((size_t)(bh_*Tt + t))*Dd + d;   // even
                        uint32_t ph = (uint32_t)h0 | ((uint32_t)h1 << 16);
                        uint32_t pl = (uint32_t)l0 | ((uint32_t)l1 << 16);
                        if (sec == 0) { *(uint32_t*)(g_qh + idx) = ph; *(uint32_t*)(g_ql + idx) = pl; }
                        else          { *(uint32_t*)(g_kh + idx) = ph; *(uint32_t*)(g_kl + idx) = pl; }
                    }
                } else if (MODE == 2) {
                    v0 = 0.5f * v0 * (1.0f + erff(v0 * 0.7071067811865475f));
                    v1 = 0.5f * v1 * (1.0f + erff(v1 * 0.7071067811865475f));
                    unsigned short h0,l0,h1,l1;
                    split_bf16(v0, h0, l0); split_bf16(v1, h1, l1);
                    size_t idx = (size_t)mrow*N + cix;
                    *(uint32_t*)(Shi + idx) = (uint32_t)h0 | ((uint32_t)h1 << 16);
                    *(uint32_t*)(Slo + idx) = (uint32_t)l0 | ((uint32_t)l1 << 16);
                } else {
                    float2 r = *(const float2*)(resid + (size_t)mrow*N + cix);
                    float2 o; o.x = v0 + r.x; o.y = v1 + r.y;
                    *(float2*)(Cout + (size_t)mrow*N + cix) = o;
                }
            }
        }
    }
}

// ---------------- mma.sync flash attention with RPE bias ----------------
// smem layout (bytes)
#define SQH 0
#define SQL 8192
#define SKH 16384
#define SKL 24576
#define SVH 32768
#define SVL 40960
#define SPH 49152
#define SPL 57344
#define SPS 65536                    // float Ps[64][66]
#define SBK (SPS + 64*66*4)          // 82432 uchar bk[64][64]
#define SRP (SBK + 4096)             // rpe 64 floats
#define SRM (SRP + 256)
#define SRL (SRM + 256)
#define SRS (SRL + 256)
#define ASM_TOT (SRS + 256)

__global__ void __launch_bounds__(256) attn_mma(const float* __restrict__ rpe_table) {
    extern __shared__ char smraw[];
    const uint32_t sb = smem_u32(smraw);
    const int tid = threadIdx.x;
    const int wid = tid >> 5, lane = tid & 31;
    const int wm = wid & 3, wn = wid >> 2;
    const int qt = blockIdx.x;
    const int bh = blockIdx.y;
    const int b_ = bh >> 3, h = bh & 7;
    const int hp = bh >> 5, bp = bh & 31;
    const int t0 = qt << 6;

    float* rpe = (float*)(smraw + SRP);
    float* row_m = (float*)(smraw + SRM);
    float* row_l = (float*)(smraw + SRL);
    float* row_sc = (float*)(smraw + SRS);
    float* Ps = (float*)(smraw + SPS);
    unsigned char* bkt = (unsigned char*)(smraw + SBK);

    if (tid < NBUCKETS) rpe[tid] = rpe_table[hp*NBUCKETS + tid];
    if (tid < 64) { row_m[tid] = -INFINITY; row_l[tid] = 0.0f; }

    const int ldr = tid >> 3, ldu = tid & 7;

    // Q tiles (hi/lo) via cp.async
    {
        const __nv_bfloat16* qh = g_qh + ((size_t)bh*Tt + t0)*Dd;
        const __nv_bfloat16* ql = g_ql + ((size_t)bh*Tt + t0)*Dd;
#pragma unroll
        for (int p = 0; p < 2; p++) {
            int r = ldr + (p << 5);
            uint32_t d = swz128((uint32_t)(r << 7) + (ldu << 4));
            cp16(sb + SQH + d, qh + (size_t)r*Dd + (ldu << 3));
            cp16(sb + SQL + d, ql + (size_t)r*Dd + (ldu << 3));
        }
        cp_commit();
    }

    const int grp = lane >> 3, rim = lane & 7;
    const int arow0 = (wm << 4) + ((grp & 1) << 3) + rim;   // A frag rows (m16)
    const int aku0  = grp >> 1;
    const int brow0 = (wn << 5) + ((grp >> 1) << 3) + rim;  // B frag rows (n16), +nt2*16
    const int bku0  = grp & 1;

    float O[4][4] = {};
    const unsigned char* bkb = g_bucket + (size_t)bp*Tt*Tt;
    const int r0 = wm*16 + (lane >> 2);

    for (int s0 = 0; s0 < Tt; s0 += 64) {
        __syncthreads();   // protect prior chunk's smem reads
        // K + VT tiles
        {
            const __nv_bfloat16* kh = g_kh + ((size_t)bh*Tt + s0)*Dd;
            const __nv_bfloat16* kl = g_kl + ((size_t)bh*Tt + s0)*Dd;
            const __nv_bfloat16* vh = g_vth + (size_t)bh*Dd*512 + s0;
            const __nv_bfloat16* vl = g_vtl + (size_t)bh*Dd*512 + s0;
#pragma unroll
            for (int p = 0; p < 2; p++) {
                int r = ldr + (p << 5);
                uint32_t d = swz128((uint32_t)(r << 7) + (ldu << 4));
                cp16(sb + SKH + d, kh + (size_t)r*Dd + (ldu << 3));
                cp16(sb + SKL + d, kl + (size_t)r*Dd + (ldu << 3));
                cp16(sb + SVH + d, vh + (size_t)r*512 + (ldu << 3));
                cp16(sb + SVL + d, vl + (size_t)r*512 + (ldu << 3));
            }
            cp_commit();
        }
        // bucket tile
#pragma unroll
        for (int it = 0; it < 4; it++) {
            int f = tid + it*256;
            int r = f >> 4;
            int c4 = (f & 15) << 2;
            uchar4 u4 = make_uchar4(0,0,0,0);
            if (t0 + r < Tt && s0 + c4 < Tt)
                u4 = *(const uchar4*)(bkb + (size_t)(t0 + r)*Tt + s0 + c4);
            *(uchar4*)(bkt + r*64 + c4) = u4;
        }
        cp_wait<0>();
        __syncthreads();

        // ---- S = Q K^T (3-term split) ----
        float sacc[4][4] = {};
#pragma unroll
        for (int ks = 0; ks < 4; ks++) {
            uint32_t qhf[4], qlf[4];
            uint32_t aoff = swz128((uint32_t)(arow0 << 7) + ((aku0 + (ks << 1)) << 4));
            LDSM4(qhf, sb + SQH + aoff);
            LDSM4(qlf, sb + SQL + aoff);
#pragma unroll
            for (int nt2 = 0; nt2 < 2; nt2++) {
                uint32_t khf[4], klf[4];
                uint32_t boff = swz128((uint32_t)((brow0 + (nt2 << 4)) << 7) + ((bku0 + (ks << 1)) << 4));
                LDSM4(khf, sb + SKH + boff);
                LDSM4(klf, sb + SKL + boff);
#pragma unroll
                for (int hv = 0; hv < 2; hv++) {
                    int nt = nt2*2 + hv;
                    MMA16816(sacc[nt], qhf, khf[hv*2], khf[hv*2+1]);
                    MMA16816(sacc[nt], qhf, klf[hv*2], klf[hv*2+1]);
                    MMA16816(sacc[nt], qlf, khf[hv*2], khf[hv*2+1]);
                }
            }
        }
        // write S (scaled + rpe bias, OOB -> -inf)
#pragma unroll
        for (int nt = 0; nt < 4; nt++) {
            int c0 = wn*32 + nt*8 + ((lane & 3) << 1);
            bool oob0 = (s0 + c0 >= Tt), oob1 = (s0 + c0 + 1 >= Tt);
#pragma unroll
            for (int rr = 0; rr < 2; rr++) {
                int r = r0 + rr*8;
                float v0 = sacc[nt][rr*2+0]*0.125f + rpe[bkt[r*64 + c0]];
                float v1 = sacc[nt][rr*2+1]*0.125f + rpe[bkt[r*64 + c0 + 1]];
                if (oob0) v0 = -INFINITY;
                if (oob1) v1 = -INFINITY;
                float2 o; o.x = v0; o.y = v1;
                *(float2*)&Ps[r*66 + c0] = o;
            }
        }
        __syncthreads();

        // ---- online softmax (4 threads per row) ----
        {
            int r = tid >> 2, qq = tid & 3;
            int cbase = qq << 4;
            float mx = -INFINITY;
#pragma unroll
            for (int u = 0; u < 16; u++) mx = fmaxf(mx, Ps[r*66 + cbase + u]);
            mx = fmaxf(mx, __shfl_xor_sync(0xffffffffu, mx, 1));
            mx = fmaxf(mx, __shfl_xor_sync(0xffffffffu, mx, 2));
            float m_old = row_m[r];
            float m_new = fmaxf(m_old, mx);
            float ssum = 0.f;
#pragma unroll
            for (int u = 0; u < 16; u++) {
                float p = __expf(Ps[r*66 + cbase + u] - m_new);
                Ps[r*66 + cbase + u] = p;
                ssum += p;
            }
            ssum += __shfl_xor_sync(0xffffffffu, ssum, 1);
            ssum += __shfl_xor_sync(0xffffffffu, ssum, 2);
            if (qq == 0) {
                float sc = __expf(m_old - m_new);
                row_sc[r] = sc;
                row_l[r] = row_l[r]*sc + ssum;
                row_m[r] = m_new;
            }
        }
        __syncthreads();

        // ---- convert P -> bf16 hi/lo (swizzled) ----
        {
            int r = tid >> 2, cbase = (tid & 3) << 4;
#pragma unroll
            for (int u = 0; u < 16; u++) {
                int c = cbase + u;
                float p = Ps[r*66 + c];
                unsigned short ph, pl;
                split_bf16(p, ph, pl);
                uint32_t off = swz128((uint32_t)(r << 7) + (c << 1));
                *(unsigned short*)(smraw + SPH + off) = ph;
                *(unsigned short*)(smraw + SPL + off) = pl;
            }
        }
        __syncthreads();

        // ---- O = O*scale + P V (3-term split) ----
        {
            float sc0 = row_sc[r0], sc1 = row_sc[r0 + 8];
#pragma unroll
            for (int nt = 0; nt < 4; nt++) {
                O[nt][0] *= sc0; O[nt][1] *= sc0;
                O[nt][2] *= sc1; O[nt][3] *= sc1;
            }
#pragma unroll
            for (int ks = 0; ks < 4; ks++) {
                uint32_t phf[4], plf[4];
                uint32_t aoff = swz128((uint32_t)(arow0 << 7) + ((aku0 + (ks << 1)) << 4));
                LDSM4(phf, sb + SPH + aoff);
                LDSM4(plf, sb + SPL + aoff);
#pragma unroll
                for (int nt2 = 0; nt2 < 2; nt2++) {
                    uint32_t vhf[4], vlf[4];
                    uint32_t boff = swz128((uint32_t)((brow0 + (nt2 << 4)) << 7) + ((bku0 + (ks << 1)) << 4));
                    LDSM4(vhf, sb + SVH + boff);
                    LDSM4(vlf, sb + SVL + boff);
#pragma unroll
                    for (int hv = 0; hv < 2; hv++) {
                        int nt = nt2*2 + hv;
                        MMA16816(O[nt], phf, vhf[hv*2], vhf[hv*2+1]);
                        MMA16816(O[nt], phf, vlf[hv*2], vlf[hv*2+1]);
                        MMA16816(O[nt], plf, vhf[hv*2], vhf[hv*2+1]);
                    }
                }
            }
        }
    }

    // ---- finalize: /l, split, store into g_ahi/g_alo (y) ----
    {
        float inv0 = 1.0f / row_l[r0];
        float inv1 = 1.0f / row_l[r0 + 8];
        int t_a = t0 + r0, t_b = t_a + 8;
#pragma unroll
        for (int nt = 0; nt < 4; nt++) {
            int c0 = wn*32 + nt*8 + ((lane & 3) << 1);
            if (t_a < Tt) {
                unsigned short h0,l0,h1,l1;
                split_bf16(O[nt][0]*inv0, h0, l0);
                split_bf16(O[nt][1]*inv0, h1, l1);
                size_t idx = ((size_t)(b_*Tt + t_a))*Cc + h*Dd + c0;
                *(uint32_t*)(g_ahi + idx) = (uint32_t)h0 | ((uint32_t)h1 << 16);
                *(uint32_t*)(g_alo + idx) = (uint32_t)l0 | ((uint32_t)l1 << 16);
            }
            if (t_b < Tt) {
                unsigned short h0,l0,h1,l1;
                split_bf16(O[nt][2]*inv1, h0, l0);
                split_bf16(O[nt][3]*inv1, h1, l1);
                size_t idx = ((size_t)(b_*Tt + t_b))*Cc + h*Dd + c0;
                *(uint32_t*)(g_ahi + idx) = (uint32_t)h0 | ((uint32_t)h1 << 16);
                *(uint32_t*)(g_alo + idx) = (uint32_t)l0 | ((uint32_t)l1 << 16);
            }
        }
    }
}

// ---------------- layernorm (optionally emits bf16 split) ----------------
__global__ void __launch_bounds__(256) ln_kernel(const float* __restrict__ in,
    const float* __restrict__ w, const float* __restrict__ b, float* __restrict__ out,
    __nv_bfloat16* __restrict__ shi, __nv_bfloat16* __restrict__ slo)
{
    __shared__ float red[8];
    int row = blockIdx.x;
    const float* x = in + (size_t)row*Cc;
    int tid = threadIdx.x;
    float v0 = x[tid], v1 = x[tid + 256];
    float s = v0 + v1;
#pragma unroll
    for (int o = 16; o > 0; o >>= 1) s += __shfl_xor_sync(0xffffffffu, s, o);
    if ((tid & 31) == 0) red[tid >> 5] = s;
    __syncthreads();
    float tot = red[0]+red[1]+red[2]+red[3]+red[4]+red[5]+red[6]+red[7];
    float mean = tot * (1.0f/512.0f);
    float d0 = v0 - mean, d1 = v1 - mean;
    float s2 = d0*d0 + d1*d1;
#pragma unroll
    for (int o = 16; o > 0; o >>= 1) s2 += __shfl_xor_sync(0xffffffffu, s2, o);
    __syncthreads();
    if ((tid & 31) == 0) red[tid >> 5] = s2;
    __syncthreads();
    float tot2 = red[0]+red[1]+red[2]+red[3]+red[4]+red[5]+red[6]+red[7];
    float inv = rsqrtf(tot2 * (1.0f/512.0f) + 1e-5f);
    float o0 = d0*inv*w[tid]       + b[tid];
    float o1 = d1*inv*w[tid + 256] + b[tid + 256];
    out[(size_t)row*Cc + tid]       = o0;
    out[(size_t)row*Cc + tid + 256] = o1;
    if (shi) {
        unsigned short h0,l0,h1,l1;
        split_bf16(o0, h0, l0); split_bf16(o1, h1, l1);
        shi[(size_t)row*Cc + tid]       = __ushort_as_bfloat16(h0);
        shi[(size_t)row*Cc + tid + 256] = __ushort_as_bfloat16(h1);
        slo[(size_t)row*Cc + tid]       = __ushort_as_bfloat16(l0);
        slo[(size_t)row*Cc + tid + 256] = __ushort_as_bfloat16(l1);
    }
}

// ---------------- launch ----------------
extern "C" void kernel_launch(void* const* d_in, const int* in_sizes, int n_in,
                              void* d_out, int out_size) {
    (void)in_sizes; (void)n_in; (void)out_size;
    const float* x         = (const float*)d_in[0];
    const int*   ct        = (const int*)  d_in[1];
    const float* w_attn    = (const float*)d_in[2];
    const float* b_attn    = (const float*)d_in[3];
    const float* w_proj    = (const float*)d_in[4];
    const float* b_proj    = (const float*)d_in[5];
    const float* rpe_table = (const float*)d_in[6];
    const float* ln1_w     = (const float*)d_in[7];
    const float* ln1_b     = (const float*)d_in[8];
    const float* ln2_w     = (const float*)d_in[9];
    const float* ln2_b     = (const float*)d_in[10];
    const float* w_fc      = (const float*)d_in[11];
    const float* b_fc      = (const float*)d_in[12];
    const float* w_fc2     = (const float*)d_in[13];
    const float* b_fc2     = (const float*)d_in[14];
    float* out = (float*)d_out;

    float *res_, *x1_, *res2_;
    cudaGetSymbolAddress((void**)&res_,  g_res);
    cudaGetSymbolAddress((void**)&x1_,   g_x1);
    cudaGetSymbolAddress((void**)&res2_, g_res2);
    __nv_bfloat16 *ahi, *alo, *bhi, *blo;
    __nv_bfloat16 *wha, *wla, *whp, *wlp, *whf, *wlf, *whf2, *wlf2;
    cudaGetSymbolAddress((void**)&ahi,  g_ahi);
    cudaGetSymbolAddress((void**)&alo,  g_alo);
    cudaGetSymbolAddress((void**)&bhi,  g_bhi);
    cudaGetSymbolAddress((void**)&blo,  g_blo);
    cudaGetSymbolAddress((void**)&wha,  g_wh_attn);
    cudaGetSymbolAddress((void**)&wla,  g_wl_attn);
    cudaGetSymbolAddress((void**)&whp,  g_wh_proj);
    cudaGetSymbolAddress((void**)&wlp,  g_wl_proj);
    cudaGetSymbolAddress((void**)&whf,  g_wh_fc);
    cudaGetSymbolAddress((void**)&wlf,  g_wl_fc);
    cudaGetSymbolAddress((void**)&whf2, g_wh_fc2);
    cudaGetSymbolAddress((void**)&wlf2, g_wl_fc2);

    cudaFuncSetAttribute(attn_mma, cudaFuncAttributeMaxDynamicSharedMemorySize, ASM_TOT);
    cudaFuncSetAttribute(mma_gemm<0>, cudaFuncAttributeMaxDynamicSharedMemorySize, GSM_TOT);
    cudaFuncSetAttribute(mma_gemm<1>, cudaFuncAttributeMaxDynamicSharedMemorySize, GSM_TOT);
    cudaFuncSetAttribute(mma_gemm<2>, cudaFuncAttributeMaxDynamicSharedMemorySize, GSM_TOT);
    cudaFuncSetAttribute(mma_gemm<3>, cudaFuncAttributeMaxDynamicSharedMemorySize, GSM_TOT);

    bucket_kernel<<<(Bb*Tt*Tt + 255)/256, 256>>>(ct);

    // weight transpose + split
    wconv_kernel<<<dim3(1536/32, 512/32), 256>>>(w_attn, wha, wla, 512, 1536);
    wconv_kernel<<<dim3(512/32, 512/32),  256>>>(w_proj, whp, wlp, 512, 512);
    wconv_kernel<<<dim3(1024/32, 512/32), 256>>>(w_fc,   whf, wlf, 512, 1024);
    wconv_kernel<<<dim3(512/32, 1024/32), 256>>>(w_fc2,  whf2, wlf2, 1024, 512);

    // x split -> qkv gemm (epilogue scatters split q/k/vT) -> attention (emits y split)
    aconv_kernel<<<(Mrows*Cc/4 + 255)/256, 256>>>((const float4*)x, (uint2*)ahi, (uint2*)alo, Mrows*Cc/4);
    mma_gemm<0><<<dim3(12, 125), 256, GSM_TOT>>>(ahi, alo, wha, wla, b_attn,
                                                 nullptr, nullptr, nullptr, nullptr, Mrows, 3*Cc, Cc);
    attn_mma<<<dim3(8, Bb*Hh), 256, ASM_TOT>>>(rpe_table);

    // proj + resid -> ln1 (emits x1 split)
    mma_gemm<1><<<dim3(4, 125), 256, GSM_TOT>>>(ahi, alo, whp, wlp, b_proj,
                                                res_, x, nullptr, nullptr, Mrows, Cc, Cc);
    ln_kernel<<<Mrows, 256>>>(res_, ln1_w, ln1_b, x1_, ahi, alo);

    // fc + gelu (emits h split) -> fc2 + resid -> ln2
    mma_gemm<2><<<dim3(8, 125), 256, GSM_TOT>>>(ahi, alo, whf, wlf, b_fc,
                                                nullptr, nullptr, bhi, blo, Mrows, 2*Cc, Cc);
    mma_gemm<3><<<dim3(4, 125), 256, GSM_TOT>>>(bhi, blo, whf2, wlf2, b_fc2,
                                                res2_, x1_, nullptr, nullptr, Mrows, Cc, 2*Cc);
    ln_kernel<<<Mrows, 256>>>(res2_, ln2_w, ln2_b, out, nullptr, nullptr);
}

// round 7
// speedup vs baseline: 2.7720x; 1.1310x over previous
#include <cuda_runtime.h>
#include <cuda_bf16.h>
#include <math.h>
#include <stdint.h>

#define Bb 32
#define Tt 500
#define Cc 512
#define Hh 8
#define Dd 64
#define Mrows (Bb*Tt)
#define NBUCKETS 49

// ---------------- scratch (static device globals; zero-initialized) ----------------
__device__ float g_res [(size_t)Mrows*Cc];
__device__ float g_x1  [(size_t)Mrows*Cc];
__device__ float g_res2[(size_t)Mrows*Cc];
__device__ unsigned char g_bucket[(size_t)Bb*Tt*Tt + 64];

// bf16 split buffers (padded; pad region stays zero)
__device__ __nv_bfloat16 g_qh[(size_t)(Bb*Hh*Tt + 64)*Dd], g_ql[(size_t)(Bb*Hh*Tt + 64)*Dd];
__device__ __nv_bfloat16 g_kh[(size_t)(Bb*Hh*Tt + 64)*Dd], g_kl[(size_t)(Bb*Hh*Tt + 64)*Dd];
__device__ __nv_bfloat16 g_vth[(size_t)Bb*Hh*Dd*512 + 1024], g_vtl[(size_t)Bb*Hh*Dd*512 + 1024];
__device__ __nv_bfloat16 g_ahi[(size_t)Mrows*1024 + 1024], g_alo[(size_t)Mrows*1024 + 1024];
__device__ __nv_bfloat16 g_bhi[(size_t)Mrows*1024 + 1024], g_blo[(size_t)Mrows*1024 + 1024];
__device__ __nv_bfloat16 g_wh_attn[1536*512], g_wl_attn[1536*512];
__device__ __nv_bfloat16 g_wh_proj[512*512],  g_wl_proj[512*512];
__device__ __nv_bfloat16 g_wh_fc[1024*512],   g_wl_fc[1024*512];
__device__ __nv_bfloat16 g_wh_fc2[512*1024],  g_wl_fc2[512*1024];

// ---------------- helpers ----------------
__device__ __forceinline__ uint32_t smem_u32(const void* p) {
    uint32_t a;
    asm("{ .reg .u64 t; cvta.to.shared.u64 t, %1; cvt.u32.u64 %0, t; }" : "=r"(a) : "l"(p));
    return a;
}
__device__ __forceinline__ uint32_t swz128(uint32_t o) { return o ^ ((o >> 3) & 0x70); }

__device__ __forceinline__ void cp16(uint32_t dst, const void* src) {
    asm volatile("cp.async.cg.shared.global [%0], [%1], 16;" :: "r"(dst), "l"(src));
}
__device__ __forceinline__ void cp_commit() {
    asm volatile("cp.async.commit_group;" ::: "memory");
}
template<int N> __device__ __forceinline__ void cp_wait() {
    asm volatile("cp.async.wait_group %0;" :: "n"(N) : "memory");
}

#define LDSM4(r, addr) \
    asm volatile("ldmatrix.sync.aligned.m8n8.x4.shared.b16 {%0,%1,%2,%3}, [%4];" \
        : "=r"((r)[0]),"=r"((r)[1]),"=r"((r)[2]),"=r"((r)[3]) : "r"(addr))

#define MMA16816(d, a, b0, b1) \
    asm volatile("mma.sync.aligned.m16n8k16.row.col.f32.bf16.bf16.f32 " \
        "{%0,%1,%2,%3}, {%4,%5,%6,%7}, {%8,%9}, {%0,%1,%2,%3};" \
        : "+f"((d)[0]),"+f"((d)[1]),"+f"((d)[2]),"+f"((d)[3]) \
        : "r"((a)[0]),"r"((a)[1]),"r"((a)[2]),"r"((a)[3]), "r"(b0),"r"(b1))

__device__ __forceinline__ void split_bf16(float v, unsigned short& h, unsigned short& l) {
    __nv_bfloat16 hb = __float2bfloat16(v);
    __nv_bfloat16 lb = __float2bfloat16(v - __bfloat162float(hb));
    h = __bfloat16_as_ushort(hb);
    l = __bfloat16_as_ushort(lb);
}

// ---------------- bucket ids: one block per (t, b), uchar4 stores, no divisions ----
__global__ void __launch_bounds__(128) bucket_kernel(const int* __restrict__ ct) {
    const int t = blockIdx.x, b = blockIdx.y;
    const int j = threadIdx.x;          // covers s = 4j .. 4j+3
    if (j >= 125) return;               // 125 * 4 = 500 = Tt exactly
    const int2 c1 = ((const int2*)ct)[b*Tt + t];
    const int2* cs = ((const int2*)ct) + b*Tt + 4*j;
    uchar4 o;
    unsigned char* po = &o.x;
#pragma unroll
    for (int u = 0; u < 4; u++) {
        int2 c2 = cs[u];
        int dx = c1.x - c2.x, dy = c1.y - c2.y;
        float dist = sqrtf((float)(dx*dx + dy*dy));
        float rel = truncf(dist * (1.0f/12.0f));
        float idx;
        if (rel <= 12.0f) idx = rel;
        else idx = fminf(rintf(12.0f + logf(rel * (1.0f/12.0f)) * 5.7707801635558523f), 24.0f);
        po[u] = (unsigned char)(int)(idx + 24.0f);
    }
    *(uchar4*)(g_bucket + (size_t)b*(Tt*Tt) + (size_t)t*Tt + 4*j) = o;
}

// ---------------- bf16 split conversions ----------------
__global__ void __launch_bounds__(256) aconv_kernel(const float4* __restrict__ in,
    uint2* __restrict__ hi, uint2* __restrict__ lo, int n4)
{
    int i = blockIdx.x * blockDim.x + threadIdx.x;
    if (i >= n4) return;
    float4 f = in[i];
    unsigned short h0,h1,h2,h3,l0,l1,l2,l3;
    split_bf16(f.x, h0, l0); split_bf16(f.y, h1, l1);
    split_bf16(f.z, h2, l2); split_bf16(f.w, h3, l3);
    uint2 ho, lv;
    ho.x = (uint32_t)h0 | ((uint32_t)h1 << 16);
    ho.y = (uint32_t)h2 | ((uint32_t)h3 << 16);
    lv.x = (uint32_t)l0 | ((uint32_t)l1 << 16);
    lv.y = (uint32_t)l2 | ((uint32_t)l3 << 16);
    hi[i] = ho; lo[i] = lv;
}

// W [K,N] fp32 -> WT [N,K] bf16 hi/lo
__global__ void __launch_bounds__(256) wconv_kernel(const float* __restrict__ W,
    __nv_bfloat16* __restrict__ hi, __nv_bfloat16* __restrict__ lo, int K, int N)
{
    __shared__ float tile[32][33];
    int nb = blockIdx.x << 5, kb = blockIdx.y << 5;
    int tx = threadIdx.x & 31, ty = threadIdx.x >> 5;
#pragma unroll
    for (int i = 0; i < 32; i += 8)
        tile[ty + i][tx] = W[(size_t)(kb + ty + i)*N + nb + tx];
    __syncthreads();
#pragma unroll
    for (int i = 0; i < 32; i += 8) {
        float f = tile[tx][ty + i];
        unsigned short h_, l_;
        split_bf16(f, h_, l_);
        size_t o = (size_t)(nb + ty + i)*K + kb + tx;
        hi[o] = __ushort_as_bfloat16(h_); lo[o] = __ushort_as_bfloat16(l_);
    }
}

// ---- mma.sync GEMM: CTA 128x64, KC=64, split bf16, cp.async 2-stage, 2 CTAs/SM ----
#define TA 16384            // Ahi / Alo tile bytes (128 x 64 x bf16)
#define TB 8192             // Bhi / Blo tile bytes (64 x 64 x bf16)
#define STAGE_B 49152       // Ahi,Alo,Bhi,Blo
#define GSM_TOT 98304
// MODE 0: qkv split-scatter  MODE 1/3: fp32 out = val + resid  MODE 2: gelu -> split out
template<int MODE>
__global__ void __launch_bounds__(256, 2) mma_gemm(
    const __nv_bfloat16* __restrict__ Ahi, const __nv_bfloat16* __restrict__ Alo,
    const __nv_bfloat16* __restrict__ Bhi, const __nv_bfloat16* __restrict__ Blo,
    const float* __restrict__ bias, float* __restrict__ Cout,
    const float* __restrict__ resid,
    __nv_bfloat16* __restrict__ Shi, __nv_bfloat16* __restrict__ Slo,
    int M, int N, int K)
{
    extern __shared__ char smraw[];
    const uint32_t sb = smem_u32(smraw);
    const int tid = threadIdx.x;
    const int wid = tid >> 5, lane = tid & 31;
    const int wm = wid & 3, wn = wid >> 2;          // warp tile 32x32
    const int m0 = blockIdx.y << 7, n0 = blockIdx.x << 6;

    const int ldr = tid >> 3, ldu = tid & 7;

    auto issue = [&](int kc, int buf) {
        uint32_t base = sb + buf*STAGE_B;
#pragma unroll
        for (int p = 0; p < 4; p++) {               // A: 128 rows
            int row = ldr + (p << 5);
            uint32_t d = swz128((uint32_t)(row << 7) + (ldu << 4));
            size_t ao = (size_t)(m0 + row)*K + kc + (ldu << 3);
            cp16(base + d,      Ahi + ao);
            cp16(base + TA + d, Alo + ao);
        }
#pragma unroll
        for (int p = 0; p < 2; p++) {               // B: 64 rows
            int row = ldr + (p << 5);
            uint32_t d = swz128((uint32_t)(row << 7) + (ldu << 4));
            size_t bo = (size_t)(n0 + row)*K + kc + (ldu << 3);
            cp16(base + 2*TA + d,      Bhi + bo);
            cp16(base + 2*TA + TB + d, Blo + bo);
        }
        cp_commit();
    };

    float acc[2][4][4] = {};

    const int grp = lane >> 3, rim = lane & 7;
    const int arow0 = (wm << 5) + ((grp & 1) << 3) + rim;   // + mt*16
    const int aku0  = grp >> 1;
    const int brow0 = (wn << 5) + ((grp >> 1) << 3) + rim;  // + nt2*16
    const int bku0  = grp & 1;

    issue(0, 0);
    const int nch = K >> 6;
    for (int c = 0; c < nch; c++) {
        if (c + 1 < nch) { issue((c + 1) << 6, (c + 1) & 1); cp_wait<1>(); }
        else             { cp_wait<0>(); }
        __syncthreads();
        const uint32_t base = sb + (c & 1)*STAGE_B;
#pragma unroll
        for (int ks = 0; ks < 4; ks++) {
            uint32_t ah[2][4], al[2][4];
#pragma unroll
            for (int mt = 0; mt < 2; mt++) {
                uint32_t off = swz128((uint32_t)((arow0 + (mt << 4)) << 7) + ((aku0 + (ks << 1)) << 4));
                LDSM4(ah[mt], base + off);
                LDSM4(al[mt], base + TA + off);
            }
            uint32_t bh[2][4], bl[2][4];
#pragma unroll
            for (int nt2 = 0; nt2 < 2; nt2++) {
                uint32_t off = swz128((uint32_t)((brow0 + (nt2 << 4)) << 7) + ((bku0 + (ks << 1)) << 4));
                LDSM4(bh[nt2], base + 2*TA + off);
                LDSM4(bl[nt2], base + 2*TA + TB + off);
            }
#pragma unroll
            for (int mt = 0; mt < 2; mt++)
#pragma unroll
                for (int nt = 0; nt < 4; nt++) {
                    const uint32_t* fh = &bh[nt >> 1][(nt & 1) << 1];
                    const uint32_t* fl = &bl[nt >> 1][(nt & 1) << 1];
                    MMA16816(acc[mt][nt], ah[mt], fh[0], fh[1]);
                    MMA16816(acc[mt][nt], ah[mt], fl[0], fl[1]);
                    MMA16816(acc[mt][nt], al[mt], fh[0], fh[1]);
                }
        }
        __syncthreads();
    }

    // epilogue
#pragma unroll
    for (int mt = 0; mt < 2; mt++) {
#pragma unroll
        for (int half = 0; half < 2; half++) {
            int mrow = m0 + (wm << 5) + (mt << 4) + (half << 3) + (lane >> 2);
            int b_ = mrow / Tt, t = mrow - b_*Tt;
#pragma unroll
            for (int nt = 0; nt < 4; nt++) {
                int cix = n0 + (wn << 5) + (nt << 3) + ((lane & 3) << 1);
                float v0 = acc[mt][nt][half*2 + 0] + bias[cix];
                float v1 = acc[mt][nt][half*2 + 1] + bias[cix + 1];
                if (MODE == 0) {
                    unsigned short h0,l0,h1,l1;
                    split_bf16(v0, h0, l0); split_bf16(v1, h1, l1);
                    int sec = cix >> 9, cc2 = cix & 511, hh = cc2 >> 6, d = cc2 & 63;
                    int bh_ = b_*Hh + hh;
                    if (sec == 2) {
                        size_t r0i = ((size_t)(bh_*Dd + d))*512 + t;
                        size_t r1i = ((size_t)(bh_*Dd + d + 1))*512 + t;
                        g_vth[r0i] = __ushort_as_bfloat16(h0);
                        g_vth[r1i] = __ushort_as_bfloat16(h1);
                        g_vtl[r0i] = __ushort_as_bfloat16(l0);
                        g_vtl[r1i] = __ushort_as_bfloat16(l1);
                    } else {
                        size_t idx = ((size_t)(bh_*Tt + t))*Dd + d;   // even
                        uint32_t ph = (uint32_t)h0 | ((uint32_t)h1 << 16);
                        uint32_t pl = (uint32_t)l0 | ((uint32_t)l1 << 16);
                        if (sec == 0) { *(uint32_t*)(g_qh + idx) = ph; *(uint32_t*)(g_ql + idx) = pl; }
                        else          { *(uint32_t*)(g_kh + idx) = ph; *(uint32_t*)(g_kl + idx) = pl; }
                    }
                } else if (MODE == 2) {
                    v0 = 0.5f * v0 * (1.0f + erff(v0 * 0.7071067811865475f));
                    v1 = 0.5f * v1 * (1.0f + erff(v1 * 0.7071067811865475f));
                    unsigned short h0,l0,h1,l1;
                    split_bf16(v0, h0, l0); split_bf16(v1, h1, l1);
                    size_t idx = (size_t)mrow*N + cix;
                    *(uint32_t*)(Shi + idx) = (uint32_t)h0 | ((uint32_t)h1 << 16);
                    *(uint32_t*)(Slo + idx) = (uint32_t)l0 | ((uint32_t)l1 << 16);
                } else {
                    float2 r = *(const float2*)(resid + (size_t)mrow*N + cix);
                    float2 o; o.x = v0 + r.x; o.y = v1 + r.y;
                    *(float2*)(Cout + (size_t)mrow*N + cix) = o;
                }
            }
        }
    }
}

// ---------------- mma.sync flash attention with RPE bias ----------------
#define SQH 0
#define SQL 8192
#define SKH 16384
#define SKL 24576
#define SVH 32768
#define SVL 40960
#define SPH 49152
#define SPL 57344
#define SPS 65536                    // float Ps[64][66]
#define SBK (SPS + 64*66*4)
#define SRP (SBK + 4096)
#define SRM (SRP + 256)
#define SRL (SRM + 256)
#define SRS (SRL + 256)
#define ASM_TOT (SRS + 256)

__global__ void __launch_bounds__(256) attn_mma(const float* __restrict__ rpe_table) {
    extern __shared__ char smraw[];
    const uint32_t sb = smem_u32(smraw);
    const int tid = threadIdx.x;
    const int wid = tid >> 5, lane = tid & 31;
    const int wm = wid & 3, wn = wid >> 2;
    const int qt = blockIdx.x;
    const int bh = blockIdx.y;
    const int b_ = bh >> 3, h = bh & 7;
    const int hp = bh >> 5, bp = bh & 31;
    const int t0 = qt << 6;

    float* rpe = (float*)(smraw + SRP);
    float* row_m = (float*)(smraw + SRM);
    float* row_l = (float*)(smraw + SRL);
    float* row_sc = (float*)(smraw + SRS);
    float* Ps = (float*)(smraw + SPS);
    unsigned char* bkt = (unsigned char*)(smraw + SBK);

    if (tid < NBUCKETS) rpe[tid] = rpe_table[hp*NBUCKETS + tid];
    if (tid < 64) { row_m[tid] = -INFINITY; row_l[tid] = 0.0f; }

    const int ldr = tid >> 3, ldu = tid & 7;

    {
        const __nv_bfloat16* qh = g_qh + ((size_t)bh*Tt + t0)*Dd;
        const __nv_bfloat16* ql = g_ql + ((size_t)bh*Tt + t0)*Dd;
#pragma unroll
        for (int p = 0; p < 2; p++) {
            int r = ldr + (p << 5);
            uint32_t d = swz128((uint32_t)(r << 7) + (ldu << 4));
            cp16(sb + SQH + d, qh + (size_t)r*Dd + (ldu << 3));
            cp16(sb + SQL + d, ql + (size_t)r*Dd + (ldu << 3));
        }
        cp_commit();
    }

    const int grp = lane >> 3, rim = lane & 7;
    const int arow0 = (wm << 4) + ((grp & 1) << 3) + rim;
    const int aku0  = grp >> 1;
    const int brow0 = (wn << 5) + ((grp >> 1) << 3) + rim;
    const int bku0  = grp & 1;

    float O[4][4] = {};
    const unsigned char* bkb = g_bucket + (size_t)bp*Tt*Tt;
    const int r0 = wm*16 + (lane >> 2);

    for (int s0 = 0; s0 < Tt; s0 += 64) {
        __syncthreads();
        {
            const __nv_bfloat16* kh = g_kh + ((size_t)bh*Tt + s0)*Dd;
            const __nv_bfloat16* kl = g_kl + ((size_t)bh*Tt + s0)*Dd;
            const __nv_bfloat16* vh = g_vth + (size_t)bh*Dd*512 + s0;
            const __nv_bfloat16* vl = g_vtl + (size_t)bh*Dd*512 + s0;
#pragma unroll
            for (int p = 0; p < 2; p++) {
                int r = ldr + (p << 5);
                uint32_t d = swz128((uint32_t)(r << 7) + (ldu << 4));
                cp16(sb + SKH + d, kh + (size_t)r*Dd + (ldu << 3));
                cp16(sb + SKL + d, kl + (size_t)r*Dd + (ldu << 3));
                cp16(sb + SVH + d, vh + (size_t)r*512 + (ldu << 3));
                cp16(sb + SVL + d, vl + (size_t)r*512 + (ldu << 3));
            }
            cp_commit();
        }
#pragma unroll
        for (int it = 0; it < 4; it++) {
            int f = tid + it*256;
            int r = f >> 4;
            int c4 = (f & 15) << 2;
            uchar4 u4 = make_uchar4(0,0,0,0);
            if (t0 + r < Tt && s0 + c4 < Tt)
                u4 = *(const uchar4*)(bkb + (size_t)(t0 + r)*Tt + s0 + c4);
            *(uchar4*)(bkt + r*64 + c4) = u4;
        }
        cp_wait<0>();
        __syncthreads();

        // ---- S = Q K^T (3-term split) ----
        float sacc[4][4] = {};
#pragma unroll
        for (int ks = 0; ks < 4; ks++) {
            uint32_t qhf[4], qlf[4];
            uint32_t aoff = swz128((uint32_t)(arow0 << 7) + ((aku0 + (ks << 1)) << 4));
            LDSM4(qhf, sb + SQH + aoff);
            LDSM4(qlf, sb + SQL + aoff);
#pragma unroll
            for (int nt2 = 0; nt2 < 2; nt2++) {
                uint32_t khf[4], klf[4];
                uint32_t boff = swz128((uint32_t)((brow0 + (nt2 << 4)) << 7) + ((bku0 + (ks << 1)) << 4));
                LDSM4(khf, sb + SKH + boff);
                LDSM4(klf, sb + SKL + boff);
#pragma unroll
                for (int hv = 0; hv < 2; hv++) {
                    int nt = nt2*2 + hv;
                    MMA16816(sacc[nt], qhf, khf[hv*2], khf[hv*2+1]);
                    MMA16816(sacc[nt], qhf, klf[hv*2], klf[hv*2+1]);
                    MMA16816(sacc[nt], qlf, khf[hv*2], khf[hv*2+1]);
                }
            }
        }
#pragma unroll
        for (int nt = 0; nt < 4; nt++) {
            int c0 = wn*32 + nt*8 + ((lane & 3) << 1);
            bool oob0 = (s0 + c0 >= Tt), oob1 = (s0 + c0 + 1 >= Tt);
#pragma unroll
            for (int rr = 0; rr < 2; rr++) {
                int r = r0 + rr*8;
                float v0 = sacc[nt][rr*2+0]*0.125f + rpe[bkt[r*64 + c0]];
                float v1 = sacc[nt][rr*2+1]*0.125f + rpe[bkt[r*64 + c0 + 1]];
                if (oob0) v0 = -INFINITY;
                if (oob1) v1 = -INFINITY;
                float2 o; o.x = v0; o.y = v1;
                *(float2*)&Ps[r*66 + c0] = o;
            }
        }
        __syncthreads();

        // ---- online softmax ----
        {
            int r = tid >> 2, qq = tid & 3;
            int cbase = qq << 4;
            float mx = -INFINITY;
#pragma unroll
            for (int u = 0; u < 16; u++) mx = fmaxf(mx, Ps[r*66 + cbase + u]);
            mx = fmaxf(mx, __shfl_xor_sync(0xffffffffu, mx, 1));
            mx = fmaxf(mx, __shfl_xor_sync(0xffffffffu, mx, 2));
            float m_old = row_m[r];
            float m_new = fmaxf(m_old, mx);
            float ssum = 0.f;
#pragma unroll
            for (int u = 0; u < 16; u++) {
                float p = __expf(Ps[r*66 + cbase + u] - m_new);
                Ps[r*66 + cbase + u] = p;
                ssum += p;
            }
            ssum += __shfl_xor_sync(0xffffffffu, ssum, 1);
            ssum += __shfl_xor_sync(0xffffffffu, ssum, 2);
            if (qq == 0) {
                float sc = __expf(m_old - m_new);
                row_sc[r] = sc;
                row_l[r] = row_l[r]*sc + ssum;
                row_m[r] = m_new;
            }
        }
        __syncthreads();

        // ---- P -> bf16 hi/lo ----
        {
            int r = tid >> 2, cbase = (tid & 3) << 4;
#pragma unroll
            for (int u = 0; u < 16; u++) {
                int c = cbase + u;
                float p = Ps[r*66 + c];
                unsigned short ph, pl;
                split_bf16(p, ph, pl);
                uint32_t off = swz128((uint32_t)(r << 7) + (c << 1));
                *(unsigned short*)(smraw + SPH + off) = ph;
                *(unsigned short*)(smraw + SPL + off) = pl;
            }
        }
        __syncthreads();

        // ---- O = O*scale + P V ----
        {
            float sc0 = row_sc[r0], sc1 = row_sc[r0 + 8];
#pragma unroll
            for (int nt = 0; nt < 4; nt++) {
                O[nt][0] *= sc0; O[nt][1] *= sc0;
                O[nt][2] *= sc1; O[nt][3] *= sc1;
            }
#pragma unroll
            for (int ks = 0; ks < 4; ks++) {
                uint32_t phf[4], plf[4];
                uint32_t aoff = swz128((uint32_t)(arow0 << 7) + ((aku0 + (ks << 1)) << 4));
                LDSM4(phf, sb + SPH + aoff);
                LDSM4(plf, sb + SPL + aoff);
#pragma unroll
                for (int nt2 = 0; nt2 < 2; nt2++) {
                    uint32_t vhf[4], vlf[4];
                    uint32_t boff = swz128((uint32_t)((brow0 + (nt2 << 4)) << 7) + ((bku0 + (ks << 1)) << 4));
                    LDSM4(vhf, sb + SVH + boff);
                    LDSM4(vlf, sb + SVL + boff);
#pragma unroll
                    for (int hv = 0; hv < 2; hv++) {
                        int nt = nt2*2 + hv;
                        MMA16816(O[nt], phf, vhf[hv*2], vhf[hv*2+1]);
                        MMA16816(O[nt], phf, vlf[hv*2], vlf[hv*2+1]);
                        MMA16816(O[nt], plf, vhf[hv*2], vhf[hv*2+1]);
                    }
                }
            }
        }
    }

    // ---- finalize ----
    {
        float inv0 = 1.0f / row_l[r0];
        float inv1 = 1.0f / row_l[r0 + 8];
        int t_a = t0 + r0, t_b = t_a + 8;
#pragma unroll
        for (int nt = 0; nt < 4; nt++) {
            int c0 = wn*32 + nt*8 + ((lane & 3) << 1);
            if (t_a < Tt) {
                unsigned short h0,l0,h1,l1;
                split_bf16(O[nt][0]*inv0, h0, l0);
                split_bf16(O[nt][1]*inv0, h1, l1);
                size_t idx = ((size_t)(b_*Tt + t_a))*Cc + h*Dd + c0;
                *(uint32_t*)(g_ahi + idx) = (uint32_t)h0 | ((uint32_t)h1 << 16);
                *(uint32_t*)(g_alo + idx) = (uint32_t)l0 | ((uint32_t)l1 << 16);
            }
            if (t_b < Tt) {
                unsigned short h0,l0,h1,l1;
                split_bf16(O[nt][2]*inv1, h0, l0);
                split_bf16(O[nt][3]*inv1, h1, l1);
                size_t idx = ((size_t)(b_*Tt + t_b))*Cc + h*Dd + c0;
                *(uint32_t*)(g_ahi + idx) = (uint32_t)h0 | ((uint32_t)h1 << 16);
                *(uint32_t*)(g_alo + idx) = (uint32_t)l0 | ((uint32_t)l1 << 16);
            }
        }
    }
}

// ---------------- layernorm (optionally emits bf16 split) ----------------
__global__ void __launch_bounds__(256) ln_kernel(const float* __restrict__ in,
    const float* __restrict__ w, const float* __restrict__ b, float* __restrict__ out,
    __nv_bfloat16* __restrict__ shi, __nv_bfloat16* __restrict__ slo)
{
    __shared__ float red[8];
    int row = blockIdx.x;
    const float* x = in + (size_t)row*Cc;
    int tid = threadIdx.x;
    float v0 = x[tid], v1 = x[tid + 256];
    float s = v0 + v1;
#pragma unroll
    for (int o = 16; o > 0; o >>= 1) s += __shfl_xor_sync(0xffffffffu, s, o);
    if ((tid & 31) == 0) red[tid >> 5] = s;
    __syncthreads();
    float tot = red[0]+red[1]+red[2]+red[3]+red[4]+red[5]+red[6]+red[7];
    float mean = tot * (1.0f/512.0f);
    float d0 = v0 - mean, d1 = v1 - mean;
    float s2 = d0*d0 + d1*d1;
#pragma unroll
    for (int o = 16; o > 0; o >>= 1) s2 += __shfl_xor_sync(0xffffffffu, s2, o);
    __syncthreads();
    if ((tid & 31) == 0) red[tid >> 5] = s2;
    __syncthreads();
    float tot2 = red[0]+red[1]+red[2]+red[3]+red[4]+red[5]+red[6]+red[7];
    float inv = rsqrtf(tot2 * (1.0f/512.0f) + 1e-5f);
    float o0 = d0*inv*w[tid]       + b[tid];
    float o1 = d1*inv*w[tid + 256] + b[tid + 256];
    out[(size_t)row*Cc + tid]       = o0;
    out[(size_t)row*Cc + tid + 256] = o1;
    if (shi) {
        unsigned short h0,l0,h1,l1;
        split_bf16(o0, h0, l0); split_bf16(o1, h1, l1);
        shi[(size_t)row*Cc + tid]       = __ushort_as_bfloat16(h0);
        shi[(size_t)row*Cc + tid + 256] = __ushort_as_bfloat16(h1);
        slo[(size_t)row*Cc + tid]       = __ushort_as_bfloat16(l0);
        slo[(size_t)row*Cc + tid + 256] = __ushort_as_bfloat16(l1);
    }
}

// ---------------- launch ----------------
extern "C" void kernel_launch(void* const* d_in, const int* in_sizes, int n_in,
                              void* d_out, int out_size) {
    (void)in_sizes; (void)n_in; (void)out_size;
    const float* x         = (const float*)d_in[0];
    const int*   ct        = (const int*)  d_in[1];
    const float* w_attn    = (const float*)d_in[2];
    const float* b_attn    = (const float*)d_in[3];
    const float* w_proj    = (const float*)d_in[4];
    const float* b_proj    = (const float*)d_in[5];
    const float* rpe_table = (const float*)d_in[6];
    const float* ln1_w     = (const float*)d_in[7];
    const float* ln1_b     = (const float*)d_in[8];
    const float* ln2_w     = (const float*)d_in[9];
    const float* ln2_b     = (const float*)d_in[10];
    const float* w_fc      = (const float*)d_in[11];
    const float* b_fc      = (const float*)d_in[12];
    const float* w_fc2     = (const float*)d_in[13];
    const float* b_fc2     = (const float*)d_in[14];
    float* out = (float*)d_out;

    float *res_, *x1_, *res2_;
    cudaGetSymbolAddress((void**)&res_,  g_res);
    cudaGetSymbolAddress((void**)&x1_,   g_x1);
    cudaGetSymbolAddress((void**)&res2_, g_res2);
    __nv_bfloat16 *ahi, *alo, *bhi, *blo;
    __nv_bfloat16 *wha, *wla, *whp, *wlp, *whf, *wlf, *whf2, *wlf2;
    cudaGetSymbolAddress((void**)&ahi,  g_ahi);
    cudaGetSymbolAddress((void**)&alo,  g_alo);
    cudaGetSymbolAddress((void**)&bhi,  g_bhi);
    cudaGetSymbolAddress((void**)&blo,  g_blo);
    cudaGetSymbolAddress((void**)&wha,  g_wh_attn);
    cudaGetSymbolAddress((void**)&wla,  g_wl_attn);
    cudaGetSymbolAddress((void**)&whp,  g_wh_proj);
    cudaGetSymbolAddress((void**)&wlp,  g_wl_proj);
    cudaGetSymbolAddress((void**)&whf,  g_wh_fc);
    cudaGetSymbolAddress((void**)&wlf,  g_wl_fc);
    cudaGetSymbolAddress((void**)&whf2, g_wh_fc2);
    cudaGetSymbolAddress((void**)&wlf2, g_wl_fc2);

    cudaFuncSetAttribute(attn_mma, cudaFuncAttributeMaxDynamicSharedMemorySize, ASM_TOT);
    cudaFuncSetAttribute(mma_gemm<0>, cudaFuncAttributeMaxDynamicSharedMemorySize, GSM_TOT);
    cudaFuncSetAttribute(mma_gemm<1>, cudaFuncAttributeMaxDynamicSharedMemorySize, GSM_TOT);
    cudaFuncSetAttribute(mma_gemm<2>, cudaFuncAttributeMaxDynamicSharedMemorySize, GSM_TOT);
    cudaFuncSetAttribute(mma_gemm<3>, cudaFuncAttributeMaxDynamicSharedMemorySize, GSM_TOT);

    bucket_kernel<<<dim3(Tt, Bb), 128>>>(ct);

    // weight transpose + split
    wconv_kernel<<<dim3(1536/32, 512/32), 256>>>(w_attn, wha, wla, 512, 1536);
    wconv_kernel<<<dim3(512/32, 512/32),  256>>>(w_proj, whp, wlp, 512, 512);
    wconv_kernel<<<dim3(1024/32, 512/32), 256>>>(w_fc,   whf, wlf, 512, 1024);
    wconv_kernel<<<dim3(512/32, 1024/32), 256>>>(w_fc2,  whf2, wlf2, 1024, 512);

    // x split -> qkv gemm -> attention (emits y split)
    aconv_kernel<<<(Mrows*Cc/4 + 255)/256, 256>>>((const float4*)x, (uint2*)ahi, (uint2*)alo, Mrows*Cc/4);
    mma_gemm<0><<<dim3(24, 125), 256, GSM_TOT>>>(ahi, alo, wha, wla, b_attn,
                                                 nullptr, nullptr, nullptr, nullptr, Mrows, 3*Cc, Cc);
    attn_mma<<<dim3(8, Bb*Hh), 256, ASM_TOT>>>(rpe_table);

    // proj + resid -> ln1 (emits x1 split)
    mma_gemm<1><<<dim3(8, 125), 256, GSM_TOT>>>(ahi, alo, whp, wlp, b_proj,
                                                res_, x, nullptr, nullptr, Mrows, Cc, Cc);
    ln_kernel<<<Mrows, 256>>>(res_, ln1_w, ln1_b, x1_, ahi, alo);

    // fc + gelu (emits h split) -> fc2 + resid -> ln2
    mma_gemm<2><<<dim3(16, 125), 256, GSM_TOT>>>(ahi, alo, whf, wlf, b_fc,
                                                 nullptr, nullptr, bhi, blo, Mrows, 2*Cc, Cc);
    mma_gemm<3><<<dim3(8, 125), 256, GSM_TOT>>>(bhi, blo, whf2, wlf2, b_fc2,
                                                res2_, x1_, nullptr, nullptr, Mrows, Cc, 2*Cc);
    ln_kernel<<<Mrows, 256>>>(res2_, ln2_w, ln2_b, out, nullptr, nullptr);
}